// round 13
// baseline (speedup 1.0000x reference)
#include <cuda_runtime.h>
#include <cuda_bf16.h>
#include <math.h>
#include <stdint.h>

#define HWSZ 16384
#define GEMM_SMEM 107520
#define ATT3_SMEM 108544

// ---------------- scratch ----------------
__device__ uint32_t g_qp [4ull*512*16384];   // packed bf16: hi | lo<<16
__device__ uint32_t g_kp [4ull*512*16384];
__device__ uint32_t g_vp [4ull*256*16384];
__device__ uint32_t g_qpT[4ull*512*16384];
__device__ uint32_t g_kpT[4ull*512*16384];
__device__ uint32_t g_vpT[4ull*256*16384];
__device__ float g_outW [4ull*256*16384];
__device__ float g_outHT[4ull*256*16384];
__device__ float g_scH[256];
__device__ float g_scW[256];
__device__ float g_bnsW[512];   // [0..255]=sum, [256..511]=sumsq
__device__ float g_bnsH[512];
__device__ __nv_bfloat16 g_wph[2*640*256];   // [g][m][k]
__device__ __nv_bfloat16 g_wpl[2*640*256];
__device__ float g_bp[2*640];

// ---------------- helpers ----------------
__device__ __forceinline__ uint32_t smem_u32(const void* p) {
    uint32_t a;
    asm("{ .reg .u64 t; cvta.to.shared.u64 t, %1; cvt.u32.u64 %0, t; }" : "=r"(a) : "l"(p));
    return a;
}
#define LDSM_X4(r0, r1, r2, r3, addr) \
    asm volatile("ldmatrix.sync.aligned.m8n8.x4.shared.b16 {%0,%1,%2,%3}, [%4];" \
        : "=r"(r0), "=r"(r1), "=r"(r2), "=r"(r3) : "r"(addr))
#define LDSM_X4_T(r0, r1, r2, r3, addr) \
    asm volatile("ldmatrix.sync.aligned.m8n8.x4.trans.shared.b16 {%0,%1,%2,%3}, [%4];" \
        : "=r"(r0), "=r"(r1), "=r"(r2), "=r"(r3) : "r"(addr))
#define CP_ASYNC16(dst, src) \
    asm volatile("cp.async.cg.shared.global [%0], [%1], 16;" :: "r"(dst), "l"(src))
#define CP_COMMIT() asm volatile("cp.async.commit_group;" ::: "memory")
#define CP_WAIT1()  asm volatile("cp.async.wait_group 1;" ::: "memory")
#define CP_WAIT0()  asm volatile("cp.async.wait_group 0;" ::: "memory")

__device__ __forceinline__ void mma16816(float* d, const uint32_t* a,
                                         uint32_t b0, uint32_t b1) {
    asm volatile(
        "mma.sync.aligned.m16n8k16.row.col.f32.bf16.bf16.f32 "
        "{%0,%1,%2,%3}, {%4,%5,%6,%7}, {%8,%9}, {%0,%1,%2,%3};"
        : "+f"(d[0]), "+f"(d[1]), "+f"(d[2]), "+f"(d[3])
        : "r"(a[0]), "r"(a[1]), "r"(a[2]), "r"(a[3]), "r"(b0), "r"(b1));
}
__device__ __forceinline__ uint32_t pack_bf(float f) {
    __nv_bfloat16 h = __float2bfloat16(f);
    __nv_bfloat16 l = __float2bfloat16(f - __bfloat162float(h));
    return (uint32_t)__bfloat16_as_ushort(h) | ((uint32_t)__bfloat16_as_ushort(l) << 16);
}
__device__ __forceinline__ void split2(float a, float b, uint32_t& h, uint32_t& l) {
    __nv_bfloat16 ha = __float2bfloat16(a);
    __nv_bfloat16 hb = __float2bfloat16(b);
    __nv_bfloat16 la = __float2bfloat16(a - __bfloat162float(ha));
    __nv_bfloat16 lb = __float2bfloat16(b - __bfloat162float(hb));
    h = (uint32_t)__bfloat16_as_ushort(ha) | ((uint32_t)__bfloat16_as_ushort(hb) << 16);
    l = (uint32_t)__bfloat16_as_ushort(la) | ((uint32_t)__bfloat16_as_ushort(lb) << 16);
}
__device__ __forceinline__ void cvt4(float4 v, uint2& h, uint2& l) {
    uint32_t h0, l0, h1, l1;
    split2(v.x, v.y, h0, l0);
    split2(v.z, v.w, h1, l1);
    h.x = h0; h.y = h1; l.x = l0; l.y = l1;
}
// A chunk layout: 128 rows x 32 k bf16; row stride 64B, XOR swizzle on 16B segs
__device__ __forceinline__ uint32_t a32_addr(uint32_t tbase, int row, int kc) {
    return tbase + (uint32_t)((row << 6) + (((kc & 31) << 1) ^ (((row >> 1) & 3) << 4)));
}

// ---------------- weight pack + bf16 split (3 kernels for launch alignment) --------
__global__ void prepw_one(const float* __restrict__ w, const float* __restrict__ bias,
                          __nv_bfloat16* __restrict__ wph, __nv_bfloat16* __restrict__ wpl,
                          float* __restrict__ bp, int m_off, int M) {
    int idx = blockIdx.x * 256 + threadIdx.x;
    int per_g = M * 256;
    int g = idx / per_g;
    int r = idx - g * per_g;
    int m = r >> 8, k = r & 255;
    float wv = w[(size_t)(g*M + m) * 256 + k];
    __nv_bfloat16 h = __float2bfloat16(wv);
    size_t didx = (size_t)(g*640 + m_off + m) * 256 + k;
    wph[didx] = h;
    wpl[didx] = __float2bfloat16(wv - __bfloat162float(h));
    if (k == 0) bp[g*640 + m_off + m] = bias[g*M + m];
}

// ---- stage [128 x 32] bf16 A chunk into swizzled layout, async (256 threads) ----
__device__ __forceinline__ void stage_a32(uint32_t smb, const __nv_bfloat16* __restrict__ src,
                                          int tid) {
    #pragma unroll
    for (int it = 0; it < 2; it++) {
        int idx = it * 256 + tid;          // 0..511
        int row = idx >> 2;
        int k8 = (idx & 3) << 3;
        uint32_t byte = (uint32_t)((row << 6) + ((k8 << 1) ^ (((row >> 1) & 3) << 4)));
        CP_ASYNC16(smb + byte, src + (size_t)row * 256 + k8);
    }
}

// ---------------- fused qkv projection GEMM: 256 thr, 64 px, 2 CTAs/SM -------------
__global__ __launch_bounds__(256, 2)
void gemm_kernel(const float* __restrict__ x,
                 const __nv_bfloat16* __restrict__ wph, const __nv_bfloat16* __restrict__ wpl,
                 const float* __restrict__ bp,
                 uint32_t* __restrict__ qb, uint32_t* __restrict__ kb2, uint32_t* __restrict__ vb) {
    extern __shared__ char sm[];
    uint32_t sbase = smem_u32(sm);
    const uint32_t AHb[2] = {1024, 17408};
    const uint32_t ALb[2] = {9216, 25600};
    const uint32_t BH = 33792, BL = 70656;   // each 256 rows x 144B = 36864B, ends 107520
    int tid = threadIdx.x;
    int lane = tid & 31, wid = tid >> 5;
    int pbase = blockIdx.x * 64;
    int z = blockIdx.y;                 // b*2+g
    int b = z >> 1, g = z & 1;
    const __nv_bfloat16* wbase_h = wph + (size_t)g*640*256;
    const __nv_bfloat16* wbase_l = wpl + (size_t)g*640*256;

    // prefetch A chunk 0 (m-tile 0, k 0..31)
    stage_a32(sbase + AHb[0], wbase_h, tid);
    stage_a32(sbase + ALb[0], wbase_l, tid);
    CP_COMMIT();

    // stage B: x [k=256][64 px] f32 -> hi/lo bf16, rows stride 144B
    {
        const float* xb = x + ((size_t)b*512 + g*256) * HWSZ + pbase;
        #pragma unroll 4
        for (int it = 0; it < 16; it++) {
            int idx = it * 256 + tid;       // 0..4095 float4
            int row = idx >> 4;
            int p4  = (idx & 15) << 2;
            float4 v = *(const float4*)(xb + (size_t)row * HWSZ + p4);
            uint2 h, l;
            cvt4(v, h, l);
            uint32_t off = (uint32_t)(row * 144 + p4 * 2);
            *(uint2*)(sm + BH + off) = h;
            *(uint2*)(sm + BL + off) = l;
        }
    }

    int mb = (wid & 3) * 32;            // warp M offset (4 slots of 32 ch)
    int nb = (wid >> 2) * 32;           // warp N offset (2 slots of 32 px)
    int laneA_row = ((lane >> 3) & 1) * 8 + (lane & 7);
    int laneA_k8  = (lane >> 4) * 8;
    int bt_r = (((lane >> 3) & 1) << 3) + (lane & 7);
    int bt_c = (lane >> 4) << 3;

    float d[2][4][4];

    #pragma unroll 1
    for (int q = 0; q < 40; q++) {      // mt = q>>3, 32-k chunk = q&7
        int mt = q >> 3;
        if ((q & 7) == 0) {
            #pragma unroll
            for (int mi = 0; mi < 2; mi++)
                #pragma unroll
                for (int nj = 0; nj < 4; nj++)
                    #pragma unroll
                    for (int c = 0; c < 4; c++) d[mi][nj][c] = 0.f;
        }
        __syncthreads();                // buf[(q+1)&1] reads finished at q-1
        if (q < 39) {
            int qq = q + 1;
            size_t aoff = ((size_t)(qq >> 3) * 128) * 256 + (qq & 7) * 32;
            stage_a32(sbase + AHb[qq & 1], wbase_h + aoff, tid);
            stage_a32(sbase + ALb[qq & 1], wbase_l + aoff, tid);
            CP_COMMIT();
            CP_WAIT1();                 // chunk q landed; prefetch in flight
        } else {
            CP_WAIT0();
        }
        __syncthreads();

        uint32_t AH = sbase + AHb[q & 1];
        uint32_t AL = sbase + ALb[q & 1];
        int kbase = (q & 7) * 32;       // B global k offset

        #pragma unroll
        for (int ks = 0; ks < 2; ks++) {
            int kl = ks * 16;
            int kk = kbase + kl;
            uint32_t aH[2][4], aL[2][4];
            #pragma unroll
            for (int mi = 0; mi < 2; mi++) {
                LDSM_X4(aH[mi][0], aH[mi][1], aH[mi][2], aH[mi][3],
                        a32_addr(AH, mb + mi*16 + laneA_row, kl + laneA_k8));
                LDSM_X4(aL[mi][0], aL[mi][1], aL[mi][2], aL[mi][3],
                        a32_addr(AL, mb + mi*16 + laneA_row, kl + laneA_k8));
            }
            uint32_t bHf[2][4], bLf[2][4];
            #pragma unroll
            for (int p = 0; p < 2; p++) {
                uint32_t bd = sbase + (uint32_t)((kk + bt_r)*144 + (nb + p*16 + bt_c)*2);
                LDSM_X4_T(bHf[p][0], bHf[p][1], bHf[p][2], bHf[p][3], bd + BH);
                LDSM_X4_T(bLf[p][0], bLf[p][1], bLf[p][2], bLf[p][3], bd + BL);
            }
            #pragma unroll
            for (int mi = 0; mi < 2; mi++)
                #pragma unroll
                for (int nj = 0; nj < 4; nj++) {
                    int p = nj >> 1, qx = (nj & 1) * 2;
                    mma16816(d[mi][nj], aH[mi], bHf[p][qx], bHf[p][qx+1]);
                    mma16816(d[mi][nj], aH[mi], bLf[p][qx], bLf[p][qx+1]);
                    mma16816(d[mi][nj], aL[mi], bHf[p][qx], bHf[p][qx+1]);
                }
        }

        if ((q & 7) == 7) {
            uint32_t* dst; size_t ch0;
            if (mt < 2)      { dst = qb;  ch0 = (size_t)b*512 + g*256 + mt*128; }
            else if (mt < 4) { dst = kb2; ch0 = (size_t)b*512 + g*256 + (mt-2)*128; }
            else             { dst = vb;  ch0 = (size_t)b*256 + g*128; }
            #pragma unroll
            for (int mi = 0; mi < 2; mi++) {
                int r0 = mb + mi*16 + (lane >> 2);
                float bias0 = bp[g*640 + mt*128 + r0];
                float bias1 = bp[g*640 + mt*128 + r0 + 8];
                uint32_t* row0 = dst + (ch0 + r0)     * HWSZ + pbase;
                uint32_t* row1 = dst + (ch0 + r0 + 8) * HWSZ + pbase;
                #pragma unroll
                for (int nj = 0; nj < 4; nj++) {
                    int col = nb + nj*8 + (lane & 3)*2;
                    uint2 o0 = { pack_bf(d[mi][nj][0] + bias0), pack_bf(d[mi][nj][1] + bias0) };
                    uint2 o1 = { pack_bf(d[mi][nj][2] + bias1), pack_bf(d[mi][nj][3] + bias1) };
                    *(uint2*)(row0 + col) = o0;
                    *(uint2*)(row1 + col) = o1;
                }
            }
        }
    }
}

// ---------------- 128x128 transpose per slice (4-byte elements) ----------------
__global__ void transpose_kernel(const float* __restrict__ in, float* __restrict__ out) {
    __shared__ float t[32][33];
    int tile = blockIdx.x;
    int bx = (tile & 3) * 32, by = (tile >> 2) * 32;
    const float* ip = in  + (size_t)blockIdx.y * HWSZ;
    float*       op = out + (size_t)blockIdx.y * HWSZ;
    int x = threadIdx.x, y = threadIdx.y;
    #pragma unroll
    for (int r = 0; r < 32; r += 8)
        t[y+r][x] = ip[(size_t)(by + y + r)*128 + bx + x];
    __syncthreads();
    #pragma unroll
    for (int r = 0; r < 32; r += 8)
        op[(size_t)(bx + y + r)*128 + by + x] = t[x][y+r];
}

// ---------------- axial attention: 64 queries/CTA, 2 CTAs/SM, fused BN sums --------
__global__ __launch_bounds__(256, 2)
void attn_mma_kernel(const uint32_t* __restrict__ qp, const uint32_t* __restrict__ kp,
                     const uint32_t* __restrict__ vp, float* __restrict__ out,
                     float* __restrict__ bns) {
    extern __shared__ char smc[];
    uint32_t sb = smem_u32(smc);
    const uint32_t SQh = 0, SQl = 18432, SKh = 36864, SKl = 71680;
    float* redM = (float*)(smc + 106496);
    float* redS = (float*)(smc + 107520);
    const float SC2 = 0.08838834764831845f * 1.4426950408889634f;  // scale*log2e

    int r = blockIdx.x;
    int n = blockIdx.y >> 1, half = blockIdx.y & 1;
    int b = blockIdx.z;
    size_t qoff = ((size_t)(b*4 + n) * 128) * HWSZ + (size_t)r * 128;
    size_t voff = ((size_t)(b*4 + n) *  64) * HWSZ + (size_t)r * 128;
    int ibq = half * 64;
    int tid = threadIdx.x;
    int lane = tid & 31, wid = tid >> 5;
    int g = lane >> 2, t = lane & 3;

    {
        const uint32_t* qs = qp + qoff + ibq;
        #pragma unroll
        for (int u = 0; u < 8; u++) {
            int idx = u*256 + tid;
            int row = idx >> 4, p4 = (idx & 15) << 2;
            uint32_t off = (uint32_t)(row*144 + p4*2);
            uint4 dq = *(const uint4*)(qs + (size_t)row*HWSZ + p4);
            uint2 qh = { (dq.x & 0xffffu) | (dq.y << 16), (dq.z & 0xffffu) | (dq.w << 16) };
            uint2 ql = { (dq.x >> 16) | (dq.y & 0xffff0000u), (dq.z >> 16) | (dq.w & 0xffff0000u) };
            *(uint2*)(smc + SQh + off) = qh;
            *(uint2*)(smc + SQl + off) = ql;
        }
        const uint32_t* ks2 = kp + qoff;
        #pragma unroll
        for (int u = 0; u < 16; u++) {
            int idx = u*256 + tid;
            int row = idx >> 5, p4 = (idx & 31) << 2;
            uint32_t off = (uint32_t)(row*272 + p4*2);
            uint4 dk = *(const uint4*)(ks2 + (size_t)row*HWSZ + p4);
            uint2 kh = { (dk.x & 0xffffu) | (dk.y << 16), (dk.z & 0xffffu) | (dk.w << 16) };
            uint2 kl = { (dk.x >> 16) | (dk.y & 0xffff0000u), (dk.z >> 16) | (dk.w & 0xffff0000u) };
            *(uint2*)(smc + SKh + off) = kh;
            *(uint2*)(smc + SKl + off) = kl;
        }
    }
    __syncthreads();

    int wm = wid >> 2, wn = wid & 3;
    int m0 = wm * 32, n0 = wn * 32;
    float acc[2][4][4];
    #pragma unroll
    for (int mi = 0; mi < 2; mi++)
        #pragma unroll
        for (int nj = 0; nj < 4; nj++)
            #pragma unroll
            for (int c = 0; c < 4; c++) acc[mi][nj][c] = 0.f;

    int a_r = ((lane >> 4) << 3) + (lane & 7);
    int a_c = ((lane >> 3) & 1) << 3;
    int b_r = (((lane >> 3) & 1) << 3) + (lane & 7);
    int b_c = (lane >> 4) << 3;
    uint32_t aoff0 = (uint32_t)(a_r*144 + (m0 + a_c)*2);
    uint32_t boff0 = (uint32_t)(b_r*272 + (n0 + b_c)*2);

    #pragma unroll
    for (int ks = 0; ks < 8; ks++) {
        uint32_t kq = (uint32_t)(ks * 16 * 144);
        uint32_t kk2 = (uint32_t)(ks * 16 * 272);
        uint32_t aqh[2][4], aql[2][4];
        #pragma unroll
        for (int mi = 0; mi < 2; mi++) {
            uint32_t ad = sb + kq + aoff0 + mi*32;
            LDSM_X4_T(aqh[mi][0], aqh[mi][1], aqh[mi][2], aqh[mi][3], ad + SQh);
            LDSM_X4_T(aql[mi][0], aql[mi][1], aql[mi][2], aql[mi][3], ad + SQl);
        }
        uint32_t bkh[2][4], bkl[2][4];
        #pragma unroll
        for (int p = 0; p < 2; p++) {
            uint32_t bd = sb + kk2 + boff0 + p*32;
            LDSM_X4_T(bkh[p][0], bkh[p][1], bkh[p][2], bkh[p][3], bd + SKh);
            LDSM_X4_T(bkl[p][0], bkl[p][1], bkl[p][2], bkl[p][3], bd + SKl);
        }
        #pragma unroll
        for (int mi = 0; mi < 2; mi++)
            #pragma unroll
            for (int nj = 0; nj < 4; nj++) {
                int p = nj >> 1, q2 = (nj & 1) * 2;
                mma16816(acc[mi][nj], aqh[mi], bkh[p][q2], bkh[p][q2+1]);
                mma16816(acc[mi][nj], aqh[mi], bkl[p][q2], bkl[p][q2+1]);
                mma16816(acc[mi][nj], aql[mi], bkh[p][q2], bkh[p][q2+1]);
            }
    }

    #pragma unroll
    for (int mi = 0; mi < 2; mi++) {
        int rA = m0 + mi*16 + g, rB = rA + 8;
        float mA = -1e30f, mB = -1e30f;
        #pragma unroll
        for (int nj = 0; nj < 4; nj++) {
            mA = fmaxf(mA, fmaxf(acc[mi][nj][0], acc[mi][nj][1]));
            mB = fmaxf(mB, fmaxf(acc[mi][nj][2], acc[mi][nj][3]));
        }
        mA = fmaxf(mA, __shfl_xor_sync(0xffffffffu, mA, 1));
        mA = fmaxf(mA, __shfl_xor_sync(0xffffffffu, mA, 2));
        mB = fmaxf(mB, __shfl_xor_sync(0xffffffffu, mB, 1));
        mB = fmaxf(mB, __shfl_xor_sync(0xffffffffu, mB, 2));
        if (t == 0) { redM[rA*4 + wn] = mA; redM[rB*4 + wn] = mB; }
    }
    __syncthreads();
    #pragma unroll
    for (int mi = 0; mi < 2; mi++) {
        int rA = m0 + mi*16 + g, rB = rA + 8;
        float mxA = fmaxf(fmaxf(redM[rA*4], redM[rA*4+1]), fmaxf(redM[rA*4+2], redM[rA*4+3])) * SC2;
        float mxB = fmaxf(fmaxf(redM[rB*4], redM[rB*4+1]), fmaxf(redM[rB*4+2], redM[rB*4+3])) * SC2;
        float sA = 0.f, sB = 0.f;
        #pragma unroll
        for (int nj = 0; nj < 4; nj++) {
            float e0 = exp2f(fmaf(acc[mi][nj][0], SC2, -mxA));
            float e1 = exp2f(fmaf(acc[mi][nj][1], SC2, -mxA));
            float e2 = exp2f(fmaf(acc[mi][nj][2], SC2, -mxB));
            float e3 = exp2f(fmaf(acc[mi][nj][3], SC2, -mxB));
            acc[mi][nj][0] = e0; acc[mi][nj][1] = e1;
            acc[mi][nj][2] = e2; acc[mi][nj][3] = e3;
            sA += e0 + e1; sB += e2 + e3;
        }
        sA += __shfl_xor_sync(0xffffffffu, sA, 1);
        sA += __shfl_xor_sync(0xffffffffu, sA, 2);
        sB += __shfl_xor_sync(0xffffffffu, sB, 1);
        sB += __shfl_xor_sync(0xffffffffu, sB, 2);
        if (t == 0) { redS[rA*4 + wn] = sA; redS[rB*4 + wn] = sB; }
    }
    __syncthreads();

    #pragma unroll
    for (int mi = 0; mi < 2; mi++) {
        int rA = m0 + mi*16 + g, rB = rA + 8;
        float iA = 1.0f / (redS[rA*4] + redS[rA*4+1] + redS[rA*4+2] + redS[rA*4+3]);
        float iB = 1.0f / (redS[rB*4] + redS[rB*4+1] + redS[rB*4+2] + redS[rB*4+3]);
        #pragma unroll
        for (int nj = 0; nj < 4; nj++) {
            int j0 = n0 + nj*8 + t*2;
            uint32_t h, l;
            split2(acc[mi][nj][0]*iA, acc[mi][nj][1]*iA, h, l);
            *(uint32_t*)(smc + SQh + rA*272 + j0*2) = h;
            *(uint32_t*)(smc + SQl + rA*272 + j0*2) = l;
            split2(acc[mi][nj][2]*iB, acc[mi][nj][3]*iB, h, l);
            *(uint32_t*)(smc + SQh + rB*272 + j0*2) = h;
            *(uint32_t*)(smc + SQl + rB*272 + j0*2) = l;
        }
    }
    __syncthreads();

    {
        const uint32_t* vs = vp + voff;
        #pragma unroll
        for (int u = 0; u < 8; u++) {
            int idx = u*256 + tid;
            int row = idx >> 5, p4 = (idx & 31) << 2;
            uint32_t off = (uint32_t)(row*272 + p4*2);
            uint4 dv = *(const uint4*)(vs + (size_t)row*HWSZ + p4);
            uint2 vh = { (dv.x & 0xffffu) | (dv.y << 16), (dv.z & 0xffffu) | (dv.w << 16) };
            uint2 vl = { (dv.x >> 16) | (dv.y & 0xffff0000u), (dv.z >> 16) | (dv.w & 0xffff0000u) };
            *(uint2*)(smc + SKh + off) = vh;
            *(uint2*)(smc + SKl + off) = vl;
        }
    }
    __syncthreads();

    int c0 = (wid & 3) * 16, i0 = (wid >> 2) * 32;
    float oacc[4][4];
    #pragma unroll
    for (int nj = 0; nj < 4; nj++)
        #pragma unroll
        for (int c = 0; c < 4; c++) oacc[nj][c] = 0.f;

    int ar2 = (((lane >> 3) & 1) << 3) + (lane & 7);
    int ac2 = (lane >> 4) << 3;
    int br2 = ((lane >> 4) << 3) + (lane & 7);
    int bc2 = ((lane >> 3) & 1) << 3;

    #pragma unroll
    for (int ks = 0; ks < 8; ks++) {
        int kb = ks * 16;
        uint32_t avh[4], avl[4];
        {
            uint32_t ad = sb + (uint32_t)((c0 + ar2)*272 + (kb + ac2)*2);
            LDSM_X4(avh[0], avh[1], avh[2], avh[3], ad + SKh);
            LDSM_X4(avl[0], avl[1], avl[2], avl[3], ad + SKl);
        }
        uint32_t bah[2][4], bal[2][4];
        #pragma unroll
        for (int ib2 = 0; ib2 < 2; ib2++) {
            uint32_t bd = sb + (uint32_t)((i0 + ib2*16 + br2)*272 + (kb + bc2)*2);
            LDSM_X4(bah[ib2][0], bah[ib2][1], bah[ib2][2], bah[ib2][3], bd + SQh);
            LDSM_X4(bal[ib2][0], bal[ib2][1], bal[ib2][2], bal[ib2][3], bd + SQl);
        }
        #pragma unroll
        for (int nj = 0; nj < 4; nj++) {
            int ib2 = nj >> 1, q2 = (nj & 1) * 2;
            mma16816(oacc[nj], avh, bah[ib2][q2], bah[ib2][q2+1]);
            mma16816(oacc[nj], avh, bal[ib2][q2], bal[ib2][q2+1]);
            mma16816(oacc[nj], avl, bah[ib2][q2], bah[ib2][q2+1]);
        }
    }

    {
        int cA = c0 + g, cB = cA + 8;
        float* oA = out + voff + (size_t)cA * HWSZ + ibq;
        float* oB = out + voff + (size_t)cB * HWSZ + ibq;
        #pragma unroll
        for (int nj = 0; nj < 4; nj++) {
            int i = i0 + nj*8 + t*2;
            float2 vA = { oacc[nj][0], oacc[nj][1] };
            float2 vB = { oacc[nj][2], oacc[nj][3] };
            *(float2*)(oA + i) = vA;
            *(float2*)(oB + i) = vB;
        }
    }

    if (n < 2) {
        float s0 = 0.f, q0 = 0.f, s1 = 0.f, q1 = 0.f;
        #pragma unroll
        for (int nj = 0; nj < 4; nj++) {
            s0 += oacc[nj][0] + oacc[nj][1];
            q0 += oacc[nj][0]*oacc[nj][0] + oacc[nj][1]*oacc[nj][1];
            s1 += oacc[nj][2] + oacc[nj][3];
            q1 += oacc[nj][2]*oacc[nj][2] + oacc[nj][3]*oacc[nj][3];
        }
        s0 += __shfl_xor_sync(0xffffffffu, s0, 1);
        s0 += __shfl_xor_sync(0xffffffffu, s0, 2);
        q0 += __shfl_xor_sync(0xffffffffu, q0, 1);
        q0 += __shfl_xor_sync(0xffffffffu, q0, 2);
        s1 += __shfl_xor_sync(0xffffffffu, s1, 1);
        s1 += __shfl_xor_sync(0xffffffffu, s1, 2);
        q1 += __shfl_xor_sync(0xffffffffu, q1, 1);
        q1 += __shfl_xor_sync(0xffffffffu, q1, 2);
        if (t == 0) {
            int chA = n*64 + c0 + g, chB = chA + 8;
            atomicAdd(&bns[chA], s0);       atomicAdd(&bns[256 + chA], q0);
            atomicAdd(&bns[chB], s1);       atomicAdd(&bns[256 + chB], q1);
        }
    }
}

// ---------------- BN finalize ----------------
__global__ void bn_finalize_kernel(const float* __restrict__ bnsW, const float* __restrict__ bnsH,
                                   const float* __restrict__ bnh_w, const float* __restrict__ bnh_b,
                                   const float* __restrict__ bnw_w, const float* __restrict__ bnw_b,
                                   float* __restrict__ scH, float* __restrict__ scW) {
    int tid = threadIdx.x;
    const float N = 65536.0f;
    if (tid < 128) {
        float mean = bnsW[tid] / N;
        float var  = bnsW[256 + tid] / N - mean*mean;
        float scale = bnw_w[tid] * rsqrtf(var + 1e-5f);
        scW[tid] = scale;
        scW[128 + tid] = bnw_b[tid] - mean*scale;
    } else {
        int c = tid - 128;
        float mean = bnsH[c] / N;
        float var  = bnsH[256 + c] / N - mean*mean;
        float scale = bnh_w[c] * rsqrtf(var + 1e-5f);
        scH[c] = scale;
        scH[128 + c] = bnh_b[c] - mean*scale;
    }
}

// ---------------- fused epilogue (reads oHT transposed in-kernel) ----------------
__global__ void final_fused_kernel(const float* __restrict__ x, const float* __restrict__ oht,
                                   const float* __restrict__ ow, const float* __restrict__ scH,
                                   const float* __restrict__ scW, const float* __restrict__ gamma,
                                   float* __restrict__ out) {
    __shared__ float t[32][33];
    int tile = blockIdx.x;
    int h0 = (tile >> 2) * 32, w0 = (tile & 3) * 32;
    int c = blockIdx.y, b = blockIdx.z;
    int tx = threadIdx.x, ty = threadIdx.y;
    float gm = gamma[0];

    const float* ohs = oht + (size_t)(b*256 + c) * HWSZ;
    #pragma unroll
    for (int r = 0; r < 32; r += 8)
        t[ty + r][tx] = ohs[(size_t)(w0 + ty + r)*128 + h0 + tx];
    __syncthreads();

    const float* ows = ow + (size_t)(b*256 + c) * HWSZ;
    const float* x0p = x + (size_t)(b*512 + c)       * HWSZ;
    const float* x1p = x + (size_t)(b*512 + c + 256) * HWSZ;
    float* o0p = out + (size_t)(b*512 + c)       * HWSZ;
    float* o1p = out + (size_t)(b*512 + c + 256) * HWSZ;
    bool dop = (c < 128);
    float sH = 0.f, shH = 0.f, sW = 0.f, shW = 0.f;
    if (dop) { sH = scH[c]; shH = scH[128+c]; sW = scW[c]; shW = scW[128+c]; }
    float* p0p = out + 33554432ull + (size_t)(b*128 + c) * HWSZ;
    float* p1p = out + 41943040ull + (size_t)(b*128 + c) * HWSZ;

    #pragma unroll
    for (int r = 0; r < 32; r += 8) {
        int hr = ty + r;
        size_t pix = (size_t)(h0 + hr)*128 + w0 + tx;
        float hv = t[tx][hr];
        float wv = ows[pix];
        o0p[pix] = gm*fmaxf(hv, 0.f) + x0p[pix];
        o1p[pix] = gm*fmaxf(wv, 0.f) + x1p[pix];
        if (dop) {
            p0p[pix] = hv*sH + shH;
            p1p[pix] = wv*sW + shW;
        }
    }
}

// ---------------- launch ----------------
extern "C" void kernel_launch(void* const* d_in, const int* in_sizes, int n_in,
                              void* d_out, int out_size) {
    const float* x     = (const float*)d_in[0];
    const float* wq    = (const float*)d_in[1];
    const float* bq    = (const float*)d_in[2];
    const float* wk    = (const float*)d_in[3];
    const float* bk    = (const float*)d_in[4];
    const float* wv    = (const float*)d_in[5];
    const float* bv    = (const float*)d_in[6];
    const float* bnh_w = (const float*)d_in[7];
    const float* bnh_b = (const float*)d_in[8];
    const float* bnw_w = (const float*)d_in[9];
    const float* bnw_b = (const float*)d_in[10];
    const float* gamma = (const float*)d_in[11];
    float* out = (float*)d_out;

    uint32_t *qp, *kp, *vp, *qpT, *kpT, *vpT;
    float *oW, *oHT, *scH, *scW, *bp, *bnsW, *bnsH;
    __nv_bfloat16 *wph, *wpl;
    cudaGetSymbolAddress((void**)&qp,   g_qp);
    cudaGetSymbolAddress((void**)&kp,   g_kp);
    cudaGetSymbolAddress((void**)&vp,   g_vp);
    cudaGetSymbolAddress((void**)&qpT,  g_qpT);
    cudaGetSymbolAddress((void**)&kpT,  g_kpT);
    cudaGetSymbolAddress((void**)&vpT,  g_vpT);
    cudaGetSymbolAddress((void**)&oW,   g_outW);
    cudaGetSymbolAddress((void**)&oHT,  g_outHT);
    cudaGetSymbolAddress((void**)&scH,  g_scH);
    cudaGetSymbolAddress((void**)&scW,  g_scW);
    cudaGetSymbolAddress((void**)&bnsW, g_bnsW);
    cudaGetSymbolAddress((void**)&bnsH, g_bnsH);
    cudaGetSymbolAddress((void**)&wph,  g_wph);
    cudaGetSymbolAddress((void**)&wpl,  g_wpl);
    cudaGetSymbolAddress((void**)&bp,   g_bp);

    cudaFuncSetAttribute(gemm_kernel, cudaFuncAttributeMaxDynamicSharedMemorySize, GEMM_SMEM);
    cudaFuncSetAttribute(attn_mma_kernel, cudaFuncAttributeMaxDynamicSharedMemorySize, ATT3_SMEM);

    // side stream + events for fork-join (host-side objects only; graph-capture safe)
    cudaStream_t s2;
    cudaStreamCreateWithFlags(&s2, cudaStreamNonBlocking);
    cudaEvent_t e1, e2;
    cudaEventCreateWithFlags(&e1, cudaEventDisableTiming);
    cudaEventCreateWithFlags(&e2, cudaEventDisableTiming);

    cudaMemsetAsync(bnsW, 0, 512 * sizeof(float));
    cudaMemsetAsync(bnsH, 0, 512 * sizeof(float));

    prepw_one<<<512, 256>>>(wq, bq, wph, wpl, bp, 0,   256);
    prepw_one<<<512, 256>>>(wk, bk, wph, wpl, bp, 256, 256);
    prepw_one<<<256, 256>>>(wv, bv, wph, wpl, bp, 512, 128);
    gemm_kernel<<<dim3(256, 8), 256, GEMM_SMEM>>>(x, wph, wpl, bp, qp, kp, vp);

    // fork: transposes on s2 run concurrently with W-direction attention on main stream
    cudaEventRecord(e1, 0);
    cudaStreamWaitEvent(s2, e1, 0);
    transpose_kernel<<<dim3(16, 2048), dim3(32,8), 0, s2>>>((const float*)qp, (float*)qpT);
    transpose_kernel<<<dim3(16, 2048), dim3(32,8), 0, s2>>>((const float*)kp, (float*)kpT);
    transpose_kernel<<<dim3(16, 1024), dim3(32,8), 0, s2>>>((const float*)vp, (float*)vpT);
    cudaEventRecord(e2, s2);

    attn_mma_kernel<<<dim3(128, 8, 4), 256, ATT3_SMEM>>>(qp,  kp,  vp,  oW,  bnsW);

    // join: H-direction attention needs the transposed tensors
    cudaStreamWaitEvent(0, e2, 0);
    attn_mma_kernel<<<dim3(128, 8, 4), 256, ATT3_SMEM>>>(qpT, kpT, vpT, oHT, bnsH);

    bn_finalize_kernel<<<1, 256>>>(bnsW, bnsH, bnh_w, bnh_b, bnw_w, bnw_b, scH, scW);
    final_fused_kernel<<<dim3(16, 256, 4), dim3(32, 8)>>>(x, oHT, oW, scH, scW, gamma, out);
}

// round 14
// speedup vs baseline: 1.4075x; 1.4075x over previous
#include <cuda_runtime.h>
#include <cuda_bf16.h>
#include <math.h>
#include <stdint.h>

#define HWSZ 16384
#define GEMM_SMEM 107520
#define ATT3_SMEM 108544

// ---------------- scratch ----------------
__device__ uint32_t g_qp [4ull*512*16384];   // packed bf16: hi | lo<<16
__device__ uint32_t g_kp [4ull*512*16384];
__device__ uint32_t g_vp [4ull*256*16384];
__device__ uint32_t g_qpT[4ull*512*16384];
__device__ uint32_t g_kpT[4ull*512*16384];
__device__ uint32_t g_vpT[4ull*256*16384];
__device__ float g_outW [4ull*256*16384];
__device__ float g_outHT[4ull*256*16384];
__device__ float g_scH[256];
__device__ float g_scW[256];
__device__ float g_bnsW[512];   // [0..255]=sum, [256..511]=sumsq
__device__ float g_bnsH[512];
__device__ __nv_bfloat16 g_wph[2*640*256];   // [g][m][k]
__device__ __nv_bfloat16 g_wpl[2*640*256];
__device__ float g_bp[2*640];

// ---------------- helpers ----------------
__device__ __forceinline__ uint32_t smem_u32(const void* p) {
    uint32_t a;
    asm("{ .reg .u64 t; cvta.to.shared.u64 t, %1; cvt.u32.u64 %0, t; }" : "=r"(a) : "l"(p));
    return a;
}
#define LDSM_X4(r0, r1, r2, r3, addr) \
    asm volatile("ldmatrix.sync.aligned.m8n8.x4.shared.b16 {%0,%1,%2,%3}, [%4];" \
        : "=r"(r0), "=r"(r1), "=r"(r2), "=r"(r3) : "r"(addr))
#define LDSM_X4_T(r0, r1, r2, r3, addr) \
    asm volatile("ldmatrix.sync.aligned.m8n8.x4.trans.shared.b16 {%0,%1,%2,%3}, [%4];" \
        : "=r"(r0), "=r"(r1), "=r"(r2), "=r"(r3) : "r"(addr))
#define CP_ASYNC16(dst, src) \
    asm volatile("cp.async.cg.shared.global [%0], [%1], 16;" :: "r"(dst), "l"(src))
#define CP_COMMIT() asm volatile("cp.async.commit_group;" ::: "memory")
#define CP_WAIT0()  asm volatile("cp.async.wait_group 0;" ::: "memory")

__device__ __forceinline__ void mma16816(float* d, const uint32_t* a,
                                         uint32_t b0, uint32_t b1) {
    asm volatile(
        "mma.sync.aligned.m16n8k16.row.col.f32.bf16.bf16.f32 "
        "{%0,%1,%2,%3}, {%4,%5,%6,%7}, {%8,%9}, {%0,%1,%2,%3};"
        : "+f"(d[0]), "+f"(d[1]), "+f"(d[2]), "+f"(d[3])
        : "r"(a[0]), "r"(a[1]), "r"(a[2]), "r"(a[3]), "r"(b0), "r"(b1));
}
__device__ __forceinline__ uint32_t pack_bf(float f) {
    __nv_bfloat16 h = __float2bfloat16(f);
    __nv_bfloat16 l = __float2bfloat16(f - __bfloat162float(h));
    return (uint32_t)__bfloat16_as_ushort(h) | ((uint32_t)__bfloat16_as_ushort(l) << 16);
}
__device__ __forceinline__ void split2(float a, float b, uint32_t& h, uint32_t& l) {
    __nv_bfloat16 ha = __float2bfloat16(a);
    __nv_bfloat16 hb = __float2bfloat16(b);
    __nv_bfloat16 la = __float2bfloat16(a - __bfloat162float(ha));
    __nv_bfloat16 lb = __float2bfloat16(b - __bfloat162float(hb));
    h = (uint32_t)__bfloat16_as_ushort(ha) | ((uint32_t)__bfloat16_as_ushort(hb) << 16);
    l = (uint32_t)__bfloat16_as_ushort(la) | ((uint32_t)__bfloat16_as_ushort(lb) << 16);
}
__device__ __forceinline__ void cvt4(float4 v, uint2& h, uint2& l) {
    uint32_t h0, l0, h1, l1;
    split2(v.x, v.y, h0, l0);
    split2(v.z, v.w, h1, l1);
    h.x = h0; h.y = h1; l.x = l0; l.y = l1;
}
// A chunk layout: 128 rows x 32 k bf16; row stride 64B, XOR swizzle on 16B segs
__device__ __forceinline__ uint32_t a32_addr(uint32_t tbase, int row, int kc) {
    return tbase + (uint32_t)((row << 6) + (((kc & 31) << 1) ^ (((row >> 1) & 3) << 4)));
}

// ---------------- weight pack + bf16 split ----------------
__global__ void prepw_one(const float* __restrict__ w, const float* __restrict__ bias,
                          __nv_bfloat16* __restrict__ wph, __nv_bfloat16* __restrict__ wpl,
                          float* __restrict__ bp, int m_off, int M) {
    int idx = blockIdx.x * 256 + threadIdx.x;
    int per_g = M * 256;
    int g = idx / per_g;
    int r = idx - g * per_g;
    int m = r >> 8, k = r & 255;
    float wv = w[(size_t)(g*M + m) * 256 + k];
    __nv_bfloat16 h = __float2bfloat16(wv);
    size_t didx = (size_t)(g*640 + m_off + m) * 256 + k;
    wph[didx] = h;
    wpl[didx] = __float2bfloat16(wv - __bfloat162float(h));
    if (k == 0) bp[g*640 + m_off + m] = bias[g*M + m];
}

// ---- stage [128 x 32] bf16 A chunk into swizzled layout, async (256 threads) ----
__device__ __forceinline__ void stage_a32(uint32_t smb, const __nv_bfloat16* __restrict__ src,
                                          int tid) {
    #pragma unroll
    for (int it = 0; it < 2; it++) {
        int idx = it * 256 + tid;          // 0..511
        int row = idx >> 2;
        int k8 = (idx & 3) << 3;
        uint32_t byte = (uint32_t)((row << 6) + ((k8 << 1) ^ (((row >> 1) & 3) << 4)));
        CP_ASYNC16(smb + byte, src + (size_t)row * 256 + k8);
    }
}

// ---------------- fused qkv projection GEMM: 256 thr, 64 px, 2 CTAs/SM -------------
// single-barrier pipelined A: per iter  WAIT0 -> sync -> stage(q+1) -> compute(q)
__global__ __launch_bounds__(256, 2)
void gemm_kernel(const float* __restrict__ x,
                 const __nv_bfloat16* __restrict__ wph, const __nv_bfloat16* __restrict__ wpl,
                 const float* __restrict__ bp,
                 uint32_t* __restrict__ qb, uint32_t* __restrict__ kb2, uint32_t* __restrict__ vb) {
    extern __shared__ char sm[];
    uint32_t sbase = smem_u32(sm);
    const uint32_t AHb[2] = {1024, 17408};
    const uint32_t ALb[2] = {9216, 25600};
    const uint32_t BH = 33792, BL = 70656;   // each 256 rows x 144B = 36864B, ends 107520
    int tid = threadIdx.x;
    int lane = tid & 31, wid = tid >> 5;
    int pbase = blockIdx.x * 64;
    int z = blockIdx.y;                 // b*2+g
    int b = z >> 1, g = z & 1;
    const __nv_bfloat16* wbase_h = wph + (size_t)g*640*256;
    const __nv_bfloat16* wbase_l = wpl + (size_t)g*640*256;

    // prefetch A chunk 0 (m-tile 0, k 0..31)
    stage_a32(sbase + AHb[0], wbase_h, tid);
    stage_a32(sbase + ALb[0], wbase_l, tid);
    CP_COMMIT();

    // stage B: x [k=256][64 px] f32 -> hi/lo bf16, rows stride 144B
    {
        const float* xb = x + ((size_t)b*512 + g*256) * HWSZ + pbase;
        #pragma unroll 4
        for (int it = 0; it < 16; it++) {
            int idx = it * 256 + tid;       // 0..4095 float4
            int row = idx >> 4;
            int p4  = (idx & 15) << 2;
            float4 v = *(const float4*)(xb + (size_t)row * HWSZ + p4);
            uint2 h, l;
            cvt4(v, h, l);
            uint32_t off = (uint32_t)(row * 144 + p4 * 2);
            *(uint2*)(sm + BH + off) = h;
            *(uint2*)(sm + BL + off) = l;
        }
    }

    int mb = (wid & 3) * 32;            // warp M offset (4 slots of 32 ch)
    int nb = (wid >> 2) * 32;           // warp N offset (2 slots of 32 px)
    int laneA_row = ((lane >> 3) & 1) * 8 + (lane & 7);
    int laneA_k8  = (lane >> 4) * 8;
    int bt_r = (((lane >> 3) & 1) << 3) + (lane & 7);
    int bt_c = (lane >> 4) << 3;

    float d[2][4][4];

    #pragma unroll 1
    for (int q = 0; q < 40; q++) {      // mt = q>>3, 32-k chunk = q&7
        int mt = q >> 3;
        if ((q & 7) == 0) {
            #pragma unroll
            for (int mi = 0; mi < 2; mi++)
                #pragma unroll
                for (int nj = 0; nj < 4; nj++)
                    #pragma unroll
                    for (int c = 0; c < 4; c++) d[mi][nj][c] = 0.f;
        }
        // chunk q landed (issued at iter q-1, flew under compute(q-1))
        CP_WAIT0();
        // single barrier: visibility of chunk q across threads AND
        // all compute(q-1) reads of parity (q+1)&1 are done -> safe to overwrite
        __syncthreads();
        if (q < 39) {
            int qq = q + 1;
            size_t aoff = ((size_t)(qq >> 3) * 128) * 256 + (qq & 7) * 32;
            stage_a32(sbase + AHb[qq & 1], wbase_h + aoff, tid);
            stage_a32(sbase + ALb[qq & 1], wbase_l + aoff, tid);
            CP_COMMIT();
        }

        uint32_t AH = sbase + AHb[q & 1];
        uint32_t AL = sbase + ALb[q & 1];
        int kbase = (q & 7) * 32;       // B global k offset

        #pragma unroll
        for (int ks = 0; ks < 2; ks++) {
            int kl = ks * 16;
            int kk = kbase + kl;
            uint32_t aH[2][4], aL[2][4];
            #pragma unroll
            for (int mi = 0; mi < 2; mi++) {
                LDSM_X4(aH[mi][0], aH[mi][1], aH[mi][2], aH[mi][3],
                        a32_addr(AH, mb + mi*16 + laneA_row, kl + laneA_k8));
                LDSM_X4(aL[mi][0], aL[mi][1], aL[mi][2], aL[mi][3],
                        a32_addr(AL, mb + mi*16 + laneA_row, kl + laneA_k8));
            }
            uint32_t bHf[2][4], bLf[2][4];
            #pragma unroll
            for (int p = 0; p < 2; p++) {
                uint32_t bd = sbase + (uint32_t)((kk + bt_r)*144 + (nb + p*16 + bt_c)*2);
                LDSM_X4_T(bHf[p][0], bHf[p][1], bHf[p][2], bHf[p][3], bd + BH);
                LDSM_X4_T(bLf[p][0], bLf[p][1], bLf[p][2], bLf[p][3], bd + BL);
            }
            #pragma unroll
            for (int mi = 0; mi < 2; mi++)
                #pragma unroll
                for (int nj = 0; nj < 4; nj++) {
                    int p = nj >> 1, qx = (nj & 1) * 2;
                    mma16816(d[mi][nj], aH[mi], bHf[p][qx], bHf[p][qx+1]);
                    mma16816(d[mi][nj], aH[mi], bLf[p][qx], bLf[p][qx+1]);
                    mma16816(d[mi][nj], aL[mi], bHf[p][qx], bHf[p][qx+1]);
                }
        }

        if ((q & 7) == 7) {
            uint32_t* dst; size_t ch0;
            if (mt < 2)      { dst = qb;  ch0 = (size_t)b*512 + g*256 + mt*128; }
            else if (mt < 4) { dst = kb2; ch0 = (size_t)b*512 + g*256 + (mt-2)*128; }
            else             { dst = vb;  ch0 = (size_t)b*256 + g*128; }
            #pragma unroll
            for (int mi = 0; mi < 2; mi++) {
                int r0 = mb + mi*16 + (lane >> 2);
                float bias0 = bp[g*640 + mt*128 + r0];
                float bias1 = bp[g*640 + mt*128 + r0 + 8];
                uint32_t* row0 = dst + (ch0 + r0)     * HWSZ + pbase;
                uint32_t* row1 = dst + (ch0 + r0 + 8) * HWSZ + pbase;
                #pragma unroll
                for (int nj = 0; nj < 4; nj++) {
                    int col = nb + nj*8 + (lane & 3)*2;
                    uint2 o0 = { pack_bf(d[mi][nj][0] + bias0), pack_bf(d[mi][nj][1] + bias0) };
                    uint2 o1 = { pack_bf(d[mi][nj][2] + bias1), pack_bf(d[mi][nj][3] + bias1) };
                    *(uint2*)(row0 + col) = o0;
                    *(uint2*)(row1 + col) = o1;
                }
            }
        }
    }
}

// ---------------- 128x128 transpose per slice (4-byte elements) ----------------
__global__ void transpose_kernel(const float* __restrict__ in, float* __restrict__ out) {
    __shared__ float t[32][33];
    int tile = blockIdx.x;
    int bx = (tile & 3) * 32, by = (tile >> 2) * 32;
    const float* ip = in  + (size_t)blockIdx.y * HWSZ;
    float*       op = out + (size_t)blockIdx.y * HWSZ;
    int x = threadIdx.x, y = threadIdx.y;
    #pragma unroll
    for (int r = 0; r < 32; r += 8)
        t[y+r][x] = ip[(size_t)(by + y + r)*128 + bx + x];
    __syncthreads();
    #pragma unroll
    for (int r = 0; r < 32; r += 8)
        op[(size_t)(bx + y + r)*128 + by + x] = t[x][y+r];
}

// ---------------- axial attention: 64 queries/CTA, 2 CTAs/SM, fused BN sums --------
__global__ __launch_bounds__(256, 2)
void attn_mma_kernel(const uint32_t* __restrict__ qp, const uint32_t* __restrict__ kp,
                     const uint32_t* __restrict__ vp, float* __restrict__ out,
                     float* __restrict__ bns) {
    extern __shared__ char smc[];
    uint32_t sb = smem_u32(smc);
    const uint32_t SQh = 0, SQl = 18432, SKh = 36864, SKl = 71680;
    float* redM = (float*)(smc + 106496);
    float* redS = (float*)(smc + 107520);
    const float SC2 = 0.08838834764831845f * 1.4426950408889634f;  // scale*log2e

    int r = blockIdx.x;
    int n = blockIdx.y >> 1, half = blockIdx.y & 1;
    int b = blockIdx.z;
    size_t qoff = ((size_t)(b*4 + n) * 128) * HWSZ + (size_t)r * 128;
    size_t voff = ((size_t)(b*4 + n) *  64) * HWSZ + (size_t)r * 128;
    int ibq = half * 64;
    int tid = threadIdx.x;
    int lane = tid & 31, wid = tid >> 5;
    int g = lane >> 2, t = lane & 3;

    {
        const uint32_t* qs = qp + qoff + ibq;
        #pragma unroll
        for (int u = 0; u < 8; u++) {
            int idx = u*256 + tid;
            int row = idx >> 4, p4 = (idx & 15) << 2;
            uint32_t off = (uint32_t)(row*144 + p4*2);
            uint4 dq = *(const uint4*)(qs + (size_t)row*HWSZ + p4);
            uint2 qh = { (dq.x & 0xffffu) | (dq.y << 16), (dq.z & 0xffffu) | (dq.w << 16) };
            uint2 ql = { (dq.x >> 16) | (dq.y & 0xffff0000u), (dq.z >> 16) | (dq.w & 0xffff0000u) };
            *(uint2*)(smc + SQh + off) = qh;
            *(uint2*)(smc + SQl + off) = ql;
        }
        const uint32_t* ks2 = kp + qoff;
        #pragma unroll
        for (int u = 0; u < 16; u++) {
            int idx = u*256 + tid;
            int row = idx >> 5, p4 = (idx & 31) << 2;
            uint32_t off = (uint32_t)(row*272 + p4*2);
            uint4 dk = *(const uint4*)(ks2 + (size_t)row*HWSZ + p4);
            uint2 kh = { (dk.x & 0xffffu) | (dk.y << 16), (dk.z & 0xffffu) | (dk.w << 16) };
            uint2 kl = { (dk.x >> 16) | (dk.y & 0xffff0000u), (dk.z >> 16) | (dk.w & 0xffff0000u) };
            *(uint2*)(smc + SKh + off) = kh;
            *(uint2*)(smc + SKl + off) = kl;
        }
    }
    __syncthreads();

    int wm = wid >> 2, wn = wid & 3;
    int m0 = wm * 32, n0 = wn * 32;
    float acc[2][4][4];
    #pragma unroll
    for (int mi = 0; mi < 2; mi++)
        #pragma unroll
        for (int nj = 0; nj < 4; nj++)
            #pragma unroll
            for (int c = 0; c < 4; c++) acc[mi][nj][c] = 0.f;

    int a_r = ((lane >> 4) << 3) + (lane & 7);
    int a_c = ((lane >> 3) & 1) << 3;
    int b_r = (((lane >> 3) & 1) << 3) + (lane & 7);
    int b_c = (lane >> 4) << 3;
    uint32_t aoff0 = (uint32_t)(a_r*144 + (m0 + a_c)*2);
    uint32_t boff0 = (uint32_t)(b_r*272 + (n0 + b_c)*2);

    #pragma unroll
    for (int ks = 0; ks < 8; ks++) {
        uint32_t kq = (uint32_t)(ks * 16 * 144);
        uint32_t kk2 = (uint32_t)(ks * 16 * 272);
        uint32_t aqh[2][4], aql[2][4];
        #pragma unroll
        for (int mi = 0; mi < 2; mi++) {
            uint32_t ad = sb + kq + aoff0 + mi*32;
            LDSM_X4_T(aqh[mi][0], aqh[mi][1], aqh[mi][2], aqh[mi][3], ad + SQh);
            LDSM_X4_T(aql[mi][0], aql[mi][1], aql[mi][2], aql[mi][3], ad + SQl);
        }
        uint32_t bkh[2][4], bkl[2][4];
        #pragma unroll
        for (int p = 0; p < 2; p++) {
            uint32_t bd = sb + kk2 + boff0 + p*32;
            LDSM_X4_T(bkh[p][0], bkh[p][1], bkh[p][2], bkh[p][3], bd + SKh);
            LDSM_X4_T(bkl[p][0], bkl[p][1], bkl[p][2], bkl[p][3], bd + SKl);
        }
        #pragma unroll
        for (int mi = 0; mi < 2; mi++)
            #pragma unroll
            for (int nj = 0; nj < 4; nj++) {
                int p = nj >> 1, q2 = (nj & 1) * 2;
                mma16816(acc[mi][nj], aqh[mi], bkh[p][q2], bkh[p][q2+1]);
                mma16816(acc[mi][nj], aqh[mi], bkl[p][q2], bkl[p][q2+1]);
                mma16816(acc[mi][nj], aql[mi], bkh[p][q2], bkh[p][q2+1]);
            }
    }

    #pragma unroll
    for (int mi = 0; mi < 2; mi++) {
        int rA = m0 + mi*16 + g, rB = rA + 8;
        float mA = -1e30f, mB = -1e30f;
        #pragma unroll
        for (int nj = 0; nj < 4; nj++) {
            mA = fmaxf(mA, fmaxf(acc[mi][nj][0], acc[mi][nj][1]));
            mB = fmaxf(mB, fmaxf(acc[mi][nj][2], acc[mi][nj][3]));
        }
        mA = fmaxf(mA, __shfl_xor_sync(0xffffffffu, mA, 1));
        mA = fmaxf(mA, __shfl_xor_sync(0xffffffffu, mA, 2));
        mB = fmaxf(mB, __shfl_xor_sync(0xffffffffu, mB, 1));
        mB = fmaxf(mB, __shfl_xor_sync(0xffffffffu, mB, 2));
        if (t == 0) { redM[rA*4 + wn] = mA; redM[rB*4 + wn] = mB; }
    }
    __syncthreads();
    #pragma unroll
    for (int mi = 0; mi < 2; mi++) {
        int rA = m0 + mi*16 + g, rB = rA + 8;
        float mxA = fmaxf(fmaxf(redM[rA*4], redM[rA*4+1]), fmaxf(redM[rA*4+2], redM[rA*4+3])) * SC2;
        float mxB = fmaxf(fmaxf(redM[rB*4], redM[rB*4+1]), fmaxf(redM[rB*4+2], redM[rB*4+3])) * SC2;
        float sA = 0.f, sB = 0.f;
        #pragma unroll
        for (int nj = 0; nj < 4; nj++) {
            float e0 = exp2f(fmaf(acc[mi][nj][0], SC2, -mxA));
            float e1 = exp2f(fmaf(acc[mi][nj][1], SC2, -mxA));
            float e2 = exp2f(fmaf(acc[mi][nj][2], SC2, -mxB));
            float e3 = exp2f(fmaf(acc[mi][nj][3], SC2, -mxB));
            acc[mi][nj][0] = e0; acc[mi][nj][1] = e1;
            acc[mi][nj][2] = e2; acc[mi][nj][3] = e3;
            sA += e0 + e1; sB += e2 + e3;
        }
        sA += __shfl_xor_sync(0xffffffffu, sA, 1);
        sA += __shfl_xor_sync(0xffffffffu, sA, 2);
        sB += __shfl_xor_sync(0xffffffffu, sB, 1);
        sB += __shfl_xor_sync(0xffffffffu, sB, 2);
        if (t == 0) { redS[rA*4 + wn] = sA; redS[rB*4 + wn] = sB; }
    }
    __syncthreads();

    #pragma unroll
    for (int mi = 0; mi < 2; mi++) {
        int rA = m0 + mi*16 + g, rB = rA + 8;
        float iA = 1.0f / (redS[rA*4] + redS[rA*4+1] + redS[rA*4+2] + redS[rA*4+3]);
        float iB = 1.0f / (redS[rB*4] + redS[rB*4+1] + redS[rB*4+2] + redS[rB*4+3]);
        #pragma unroll
        for (int nj = 0; nj < 4; nj++) {
            int j0 = n0 + nj*8 + t*2;
            uint32_t h, l;
            split2(acc[mi][nj][0]*iA, acc[mi][nj][1]*iA, h, l);
            *(uint32_t*)(smc + SQh + rA*272 + j0*2) = h;
            *(uint32_t*)(smc + SQl + rA*272 + j0*2) = l;
            split2(acc[mi][nj][2]*iB, acc[mi][nj][3]*iB, h, l);
            *(uint32_t*)(smc + SQh + rB*272 + j0*2) = h;
            *(uint32_t*)(smc + SQl + rB*272 + j0*2) = l;
        }
    }
    __syncthreads();

    {
        const uint32_t* vs = vp + voff;
        #pragma unroll
        for (int u = 0; u < 8; u++) {
            int idx = u*256 + tid;
            int row = idx >> 5, p4 = (idx & 31) << 2;
            uint32_t off = (uint32_t)(row*272 + p4*2);
            uint4 dv = *(const uint4*)(vs + (size_t)row*HWSZ + p4);
            uint2 vh = { (dv.x & 0xffffu) | (dv.y << 16), (dv.z & 0xffffu) | (dv.w << 16) };
            uint2 vl = { (dv.x >> 16) | (dv.y & 0xffff0000u), (dv.z >> 16) | (dv.w & 0xffff0000u) };
            *(uint2*)(smc + SKh + off) = vh;
            *(uint2*)(smc + SKl + off) = vl;
        }
    }
    __syncthreads();

    int c0 = (wid & 3) * 16, i0 = (wid >> 2) * 32;
    float oacc[4][4];
    #pragma unroll
    for (int nj = 0; nj < 4; nj++)
        #pragma unroll
        for (int c = 0; c < 4; c++) oacc[nj][c] = 0.f;

    int ar2 = (((lane >> 3) & 1) << 3) + (lane & 7);
    int ac2 = (lane >> 4) << 3;
    int br2 = ((lane >> 4) << 3) + (lane & 7);
    int bc2 = ((lane >> 3) & 1) << 3;

    #pragma unroll
    for (int ks = 0; ks < 8; ks++) {
        int kb = ks * 16;
        uint32_t avh[4], avl[4];
        {
            uint32_t ad = sb + (uint32_t)((c0 + ar2)*272 + (kb + ac2)*2);
            LDSM_X4(avh[0], avh[1], avh[2], avh[3], ad + SKh);
            LDSM_X4(avl[0], avl[1], avl[2], avl[3], ad + SKl);
        }
        uint32_t bah[2][4], bal[2][4];
        #pragma unroll
        for (int ib2 = 0; ib2 < 2; ib2++) {
            uint32_t bd = sb + (uint32_t)((i0 + ib2*16 + br2)*272 + (kb + bc2)*2);
            LDSM_X4(bah[ib2][0], bah[ib2][1], bah[ib2][2], bah[ib2][3], bd + SQh);
            LDSM_X4(bal[ib2][0], bal[ib2][1], bal[ib2][2], bal[ib2][3], bd + SQl);
        }
        #pragma unroll
        for (int nj = 0; nj < 4; nj++) {
            int ib2 = nj >> 1, q2 = (nj & 1) * 2;
            mma16816(oacc[nj], avh, bah[ib2][q2], bah[ib2][q2+1]);
            mma16816(oacc[nj], avh, bal[ib2][q2], bal[ib2][q2+1]);
            mma16816(oacc[nj], avl, bah[ib2][q2], bah[ib2][q2+1]);
        }
    }

    {
        int cA = c0 + g, cB = cA + 8;
        float* oA = out + voff + (size_t)cA * HWSZ + ibq;
        float* oB = out + voff + (size_t)cB * HWSZ + ibq;
        #pragma unroll
        for (int nj = 0; nj < 4; nj++) {
            int i = i0 + nj*8 + t*2;
            float2 vA = { oacc[nj][0], oacc[nj][1] };
            float2 vB = { oacc[nj][2], oacc[nj][3] };
            *(float2*)(oA + i) = vA;
            *(float2*)(oB + i) = vB;
        }
    }

    if (n < 2) {
        float s0 = 0.f, q0 = 0.f, s1 = 0.f, q1 = 0.f;
        #pragma unroll
        for (int nj = 0; nj < 4; nj++) {
            s0 += oacc[nj][0] + oacc[nj][1];
            q0 += oacc[nj][0]*oacc[nj][0] + oacc[nj][1]*oacc[nj][1];
            s1 += oacc[nj][2] + oacc[nj][3];
            q1 += oacc[nj][2]*oacc[nj][2] + oacc[nj][3]*oacc[nj][3];
        }
        s0 += __shfl_xor_sync(0xffffffffu, s0, 1);
        s0 += __shfl_xor_sync(0xffffffffu, s0, 2);
        q0 += __shfl_xor_sync(0xffffffffu, q0, 1);
        q0 += __shfl_xor_sync(0xffffffffu, q0, 2);
        s1 += __shfl_xor_sync(0xffffffffu, s1, 1);
        s1 += __shfl_xor_sync(0xffffffffu, s1, 2);
        q1 += __shfl_xor_sync(0xffffffffu, q1, 1);
        q1 += __shfl_xor_sync(0xffffffffu, q1, 2);
        if (t == 0) {
            int chA = n*64 + c0 + g, chB = chA + 8;
            atomicAdd(&bns[chA], s0);       atomicAdd(&bns[256 + chA], q0);
            atomicAdd(&bns[chB], s1);       atomicAdd(&bns[256 + chB], q1);
        }
    }
}

// ---------------- BN finalize ----------------
__global__ void bn_finalize_kernel(const float* __restrict__ bnsW, const float* __restrict__ bnsH,
                                   const float* __restrict__ bnh_w, const float* __restrict__ bnh_b,
                                   const float* __restrict__ bnw_w, const float* __restrict__ bnw_b,
                                   float* __restrict__ scH, float* __restrict__ scW) {
    int tid = threadIdx.x;
    const float N = 65536.0f;
    if (tid < 128) {
        float mean = bnsW[tid] / N;
        float var  = bnsW[256 + tid] / N - mean*mean;
        float scale = bnw_w[tid] * rsqrtf(var + 1e-5f);
        scW[tid] = scale;
        scW[128 + tid] = bnw_b[tid] - mean*scale;
    } else {
        int c = tid - 128;
        float mean = bnsH[c] / N;
        float var  = bnsH[256 + c] / N - mean*mean;
        float scale = bnh_w[c] * rsqrtf(var + 1e-5f);
        scH[c] = scale;
        scH[128 + c] = bnh_b[c] - mean*scale;
    }
}

// ---------------- fused epilogue (reads oHT transposed in-kernel) ----------------
__global__ void final_fused_kernel(const float* __restrict__ x, const float* __restrict__ oht,
                                   const float* __restrict__ ow, const float* __restrict__ scH,
                                   const float* __restrict__ scW, const float* __restrict__ gamma,
                                   float* __restrict__ out) {
    __shared__ float t[32][33];
    int tile = blockIdx.x;
    int h0 = (tile >> 2) * 32, w0 = (tile & 3) * 32;
    int c = blockIdx.y, b = blockIdx.z;
    int tx = threadIdx.x, ty = threadIdx.y;
    float gm = gamma[0];

    const float* ohs = oht + (size_t)(b*256 + c) * HWSZ;
    #pragma unroll
    for (int r = 0; r < 32; r += 8)
        t[ty + r][tx] = ohs[(size_t)(w0 + ty + r)*128 + h0 + tx];
    __syncthreads();

    const float* ows = ow + (size_t)(b*256 + c) * HWSZ;
    const float* x0p = x + (size_t)(b*512 + c)       * HWSZ;
    const float* x1p = x + (size_t)(b*512 + c + 256) * HWSZ;
    float* o0p = out + (size_t)(b*512 + c)       * HWSZ;
    float* o1p = out + (size_t)(b*512 + c + 256) * HWSZ;
    bool dop = (c < 128);
    float sH = 0.f, shH = 0.f, sW = 0.f, shW = 0.f;
    if (dop) { sH = scH[c]; shH = scH[128+c]; sW = scW[c]; shW = scW[128+c]; }
    float* p0p = out + 33554432ull + (size_t)(b*128 + c) * HWSZ;
    float* p1p = out + 41943040ull + (size_t)(b*128 + c) * HWSZ;

    #pragma unroll
    for (int r = 0; r < 32; r += 8) {
        int hr = ty + r;
        size_t pix = (size_t)(h0 + hr)*128 + w0 + tx;
        float hv = t[tx][hr];
        float wv = ows[pix];
        o0p[pix] = gm*fmaxf(hv, 0.f) + x0p[pix];
        o1p[pix] = gm*fmaxf(wv, 0.f) + x1p[pix];
        if (dop) {
            p0p[pix] = hv*sH + shH;
            p1p[pix] = wv*sW + shW;
        }
    }
}

// ---------------- launch (single stream — R12 structure) ----------------
extern "C" void kernel_launch(void* const* d_in, const int* in_sizes, int n_in,
                              void* d_out, int out_size) {
    const float* x     = (const float*)d_in[0];
    const float* wq    = (const float*)d_in[1];
    const float* bq    = (const float*)d_in[2];
    const float* wk    = (const float*)d_in[3];
    const float* bk    = (const float*)d_in[4];
    const float* wv    = (const float*)d_in[5];
    const float* bv    = (const float*)d_in[6];
    const float* bnh_w = (const float*)d_in[7];
    const float* bnh_b = (const float*)d_in[8];
    const float* bnw_w = (const float*)d_in[9];
    const float* bnw_b = (const float*)d_in[10];
    const float* gamma = (const float*)d_in[11];
    float* out = (float*)d_out;

    uint32_t *qp, *kp, *vp, *qpT, *kpT, *vpT;
    float *oW, *oHT, *scH, *scW, *bp, *bnsW, *bnsH;
    __nv_bfloat16 *wph, *wpl;
    cudaGetSymbolAddress((void**)&qp,   g_qp);
    cudaGetSymbolAddress((void**)&kp,   g_kp);
    cudaGetSymbolAddress((void**)&vp,   g_vp);
    cudaGetSymbolAddress((void**)&qpT,  g_qpT);
    cudaGetSymbolAddress((void**)&kpT,  g_kpT);
    cudaGetSymbolAddress((void**)&vpT,  g_vpT);
    cudaGetSymbolAddress((void**)&oW,   g_outW);
    cudaGetSymbolAddress((void**)&oHT,  g_outHT);
    cudaGetSymbolAddress((void**)&scH,  g_scH);
    cudaGetSymbolAddress((void**)&scW,  g_scW);
    cudaGetSymbolAddress((void**)&bnsW, g_bnsW);
    cudaGetSymbolAddress((void**)&bnsH, g_bnsH);
    cudaGetSymbolAddress((void**)&wph,  g_wph);
    cudaGetSymbolAddress((void**)&wpl,  g_wpl);
    cudaGetSymbolAddress((void**)&bp,   g_bp);

    cudaFuncSetAttribute(gemm_kernel, cudaFuncAttributeMaxDynamicSharedMemorySize, GEMM_SMEM);
    cudaFuncSetAttribute(attn_mma_kernel, cudaFuncAttributeMaxDynamicSharedMemorySize, ATT3_SMEM);

    cudaMemsetAsync(bnsW, 0, 512 * sizeof(float));
    cudaMemsetAsync(bnsH, 0, 512 * sizeof(float));

    prepw_one<<<512, 256>>>(wq, bq, wph, wpl, bp, 0,   256);
    prepw_one<<<512, 256>>>(wk, bk, wph, wpl, bp, 256, 256);
    prepw_one<<<256, 256>>>(wv, bv, wph, wpl, bp, 512, 128);
    // #6 (profiled): GEMM — 256 threads, 64 px per CTA, 2 CTAs/SM, 1 barrier/chunk
    gemm_kernel<<<dim3(256, 8), 256, GEMM_SMEM>>>(x, wph, wpl, bp, qp, kp, vp);

    attn_mma_kernel<<<dim3(128, 8, 4), 256, ATT3_SMEM>>>(qp,  kp,  vp,  oW,  bnsW);
    transpose_kernel<<<dim3(16, 2048), dim3(32,8)>>>((const float*)qp, (float*)qpT);
    transpose_kernel<<<dim3(16, 2048), dim3(32,8)>>>((const float*)kp, (float*)kpT);
    transpose_kernel<<<dim3(16, 1024), dim3(32,8)>>>((const float*)vp, (float*)vpT);
    attn_mma_kernel<<<dim3(128, 8, 4), 256, ATT3_SMEM>>>(qpT, kpT, vpT, oHT, bnsH);

    bn_finalize_kernel<<<1, 256>>>(bnsW, bnsH, bnh_w, bnh_b, bnw_w, bnw_b, scH, scW);
    final_fused_kernel<<<dim3(16, 256, 4), dim3(32, 8)>>>(x, oHT, oW, scH, scW, gamma, out);
}

// round 15
// speedup vs baseline: 1.6807x; 1.1941x over previous
#include <cuda_runtime.h>
#include <cuda_fp16.h>
#include <math.h>
#include <stdint.h>

#define HWSZ 16384
#define GEMM_SMEM 91136
#define ATT3_SMEM 108544

// ---------------- scratch ----------------
__device__ uint32_t g_qp [4ull*512*16384];   // packed fp16: hi | lo<<16
__device__ uint32_t g_kp [4ull*512*16384];
__device__ uint32_t g_vp [4ull*256*16384];
__device__ uint32_t g_qpT[4ull*512*16384];
__device__ uint32_t g_kpT[4ull*512*16384];
__device__ uint32_t g_vpT[4ull*256*16384];
__device__ float g_outW [4ull*256*16384];
__device__ float g_outHT[4ull*256*16384];
__device__ float g_scH[256];
__device__ float g_scW[256];
__device__ float g_bnsW[512];   // [0..255]=sum, [256..511]=sumsq
__device__ float g_bnsH[512];
__device__ __half g_wph[2*640*256];          // [g][m][k], fp16 hi only
__device__ float g_bp[2*640];

// ---------------- helpers ----------------
__device__ __forceinline__ uint32_t smem_u32(const void* p) {
    uint32_t a;
    asm("{ .reg .u64 t; cvta.to.shared.u64 t, %1; cvt.u32.u64 %0, t; }" : "=r"(a) : "l"(p));
    return a;
}
#define LDSM_X4(r0, r1, r2, r3, addr) \
    asm volatile("ldmatrix.sync.aligned.m8n8.x4.shared.b16 {%0,%1,%2,%3}, [%4];" \
        : "=r"(r0), "=r"(r1), "=r"(r2), "=r"(r3) : "r"(addr))
#define LDSM_X4_T(r0, r1, r2, r3, addr) \
    asm volatile("ldmatrix.sync.aligned.m8n8.x4.trans.shared.b16 {%0,%1,%2,%3}, [%4];" \
        : "=r"(r0), "=r"(r1), "=r"(r2), "=r"(r3) : "r"(addr))
#define CP_ASYNC16(dst, src) \
    asm volatile("cp.async.cg.shared.global [%0], [%1], 16;" :: "r"(dst), "l"(src))
#define CP_COMMIT() asm volatile("cp.async.commit_group;" ::: "memory")
#define CP_WAIT0()  asm volatile("cp.async.wait_group 0;" ::: "memory")

// fp16 x fp16 -> f32 accumulate
__device__ __forceinline__ void mma16816h(float* d, const uint32_t* a,
                                          uint32_t b0, uint32_t b1) {
    asm volatile(
        "mma.sync.aligned.m16n8k16.row.col.f32.f16.f16.f32 "
        "{%0,%1,%2,%3}, {%4,%5,%6,%7}, {%8,%9}, {%0,%1,%2,%3};"
        : "+f"(d[0]), "+f"(d[1]), "+f"(d[2]), "+f"(d[3])
        : "r"(a[0]), "r"(a[1]), "r"(a[2]), "r"(a[3]), "r"(b0), "r"(b1));
}
__device__ __forceinline__ uint32_t pack_h(float f) {
    __half h = __float2half_rn(f);
    __half l = __float2half_rn(f - __half2float(h));
    return (uint32_t)__half_as_ushort(h) | ((uint32_t)__half_as_ushort(l) << 16);
}
__device__ __forceinline__ void split2h(float a, float b, uint32_t& h, uint32_t& l) {
    __half ha = __float2half_rn(a);
    __half hb = __float2half_rn(b);
    __half la = __float2half_rn(a - __half2float(ha));
    __half lb = __float2half_rn(b - __half2float(hb));
    h = (uint32_t)__half_as_ushort(ha) | ((uint32_t)__half_as_ushort(hb) << 16);
    l = (uint32_t)__half_as_ushort(la) | ((uint32_t)__half_as_ushort(lb) << 16);
}
__device__ __forceinline__ void cvt4h(float4 v, uint2& h, uint2& l) {
    split2h(v.x, v.y, h.x, l.x);
    split2h(v.z, v.w, h.y, l.y);
}
// A chunk layout: 128 rows x 32 k fp16; row stride 64B, XOR swizzle on 16B segs
__device__ __forceinline__ uint32_t a32_addr(uint32_t tbase, int row, int kc) {
    return tbase + (uint32_t)((row << 6) + (((kc & 31) << 1) ^ (((row >> 1) & 3) << 4)));
}

// ---------------- weight pack (fp16 hi only) ----------------
__global__ void prepw_one(const float* __restrict__ w, const float* __restrict__ bias,
                          __half* __restrict__ wph, float* __restrict__ bp,
                          int m_off, int M) {
    int idx = blockIdx.x * 256 + threadIdx.x;
    int per_g = M * 256;
    int g = idx / per_g;
    int r = idx - g * per_g;
    int m = r >> 8, k = r & 255;
    float wv = w[(size_t)(g*M + m) * 256 + k];
    size_t didx = (size_t)(g*640 + m_off + m) * 256 + k;
    wph[didx] = __float2half_rn(wv);
    if (k == 0) bp[g*640 + m_off + m] = bias[g*M + m];
}

// ---- stage [128 x 32] fp16 A chunk into swizzled layout, async (256 threads) ----
__device__ __forceinline__ void stage_a32(uint32_t smb, const __half* __restrict__ src,
                                          int tid) {
    #pragma unroll
    for (int it = 0; it < 2; it++) {
        int idx = it * 256 + tid;          // 0..511
        int row = idx >> 2;
        int k8 = (idx & 3) << 3;
        uint32_t byte = (uint32_t)((row << 6) + ((k8 << 1) ^ (((row >> 1) & 3) << 4)));
        CP_ASYNC16(smb + byte, src + (size_t)row * 256 + k8);
    }
}

// ---------------- fused qkv projection GEMM: fp16 2-term, 2 CTAs/SM ---------------
// D = Wh * (Xh + Xl);  A operand = Wh only (8KB ping-pong), B = x hi/lo resident
__global__ __launch_bounds__(256, 2)
void gemm_kernel(const float* __restrict__ x,
                 const __half* __restrict__ wph, const float* __restrict__ bp,
                 uint32_t* __restrict__ qb, uint32_t* __restrict__ kb2, uint32_t* __restrict__ vb) {
    extern __shared__ char sm[];
    uint32_t sbase = smem_u32(sm);
    const uint32_t AHb[2] = {1024, 9216};
    const uint32_t BH = 17408, BL = 54272;   // each 256 rows x 144B = 36864B, ends 91136
    int tid = threadIdx.x;
    int lane = tid & 31, wid = tid >> 5;
    int pbase = blockIdx.x * 64;
    int z = blockIdx.y;                 // b*2+g
    int b = z >> 1, g = z & 1;
    const __half* wbase_h = wph + (size_t)g*640*256;

    // prefetch A chunk 0 (m-tile 0, k 0..31)
    stage_a32(sbase + AHb[0], wbase_h, tid);
    CP_COMMIT();

    // stage B: x [k=256][64 px] f32 -> fp16 hi/lo, rows stride 144B
    {
        const float* xb = x + ((size_t)b*512 + g*256) * HWSZ + pbase;
        #pragma unroll 4
        for (int it = 0; it < 16; it++) {
            int idx = it * 256 + tid;       // 0..4095 float4
            int row = idx >> 4;
            int p4  = (idx & 15) << 2;
            float4 v = *(const float4*)(xb + (size_t)row * HWSZ + p4);
            uint2 h, l;
            cvt4h(v, h, l);
            uint32_t off = (uint32_t)(row * 144 + p4 * 2);
            *(uint2*)(sm + BH + off) = h;
            *(uint2*)(sm + BL + off) = l;
        }
    }

    int mb = (wid & 3) * 32;            // warp M offset (4 slots of 32 ch)
    int nb = (wid >> 2) * 32;           // warp N offset (2 slots of 32 px)
    int laneA_row = ((lane >> 3) & 1) * 8 + (lane & 7);
    int laneA_k8  = (lane >> 4) * 8;
    int bt_r = (((lane >> 3) & 1) << 3) + (lane & 7);
    int bt_c = (lane >> 4) << 3;

    float d[2][4][4];

    #pragma unroll 1
    for (int q = 0; q < 40; q++) {      // mt = q>>3, 32-k chunk = q&7
        int mt = q >> 3;
        if ((q & 7) == 0) {
            #pragma unroll
            for (int mi = 0; mi < 2; mi++)
                #pragma unroll
                for (int nj = 0; nj < 4; nj++)
                    #pragma unroll
                    for (int c = 0; c < 4; c++) d[mi][nj][c] = 0.f;
        }
        CP_WAIT0();
        __syncthreads();
        if (q < 39) {
            int qq = q + 1;
            size_t aoff = ((size_t)(qq >> 3) * 128) * 256 + (qq & 7) * 32;
            stage_a32(sbase + AHb[qq & 1], wbase_h + aoff, tid);
            CP_COMMIT();
        }

        uint32_t AH = sbase + AHb[q & 1];
        int kbase = (q & 7) * 32;       // B global k offset

        #pragma unroll
        for (int ks = 0; ks < 2; ks++) {
            int kl = ks * 16;
            int kk = kbase + kl;
            uint32_t aH[2][4];
            #pragma unroll
            for (int mi = 0; mi < 2; mi++)
                LDSM_X4(aH[mi][0], aH[mi][1], aH[mi][2], aH[mi][3],
                        a32_addr(AH, mb + mi*16 + laneA_row, kl + laneA_k8));
            uint32_t bHf[2][4], bLf[2][4];
            #pragma unroll
            for (int p = 0; p < 2; p++) {
                uint32_t bd = sbase + (uint32_t)((kk + bt_r)*144 + (nb + p*16 + bt_c)*2);
                LDSM_X4_T(bHf[p][0], bHf[p][1], bHf[p][2], bHf[p][3], bd + BH);
                LDSM_X4_T(bLf[p][0], bLf[p][1], bLf[p][2], bLf[p][3], bd + BL);
            }
            #pragma unroll
            for (int mi = 0; mi < 2; mi++)
                #pragma unroll
                for (int nj = 0; nj < 4; nj++) {
                    int p = nj >> 1, qx = (nj & 1) * 2;
                    mma16816h(d[mi][nj], aH[mi], bHf[p][qx], bHf[p][qx+1]);
                    mma16816h(d[mi][nj], aH[mi], bLf[p][qx], bLf[p][qx+1]);
                }
        }

        if ((q & 7) == 7) {
            uint32_t* dst; size_t ch0;
            if (mt < 2)      { dst = qb;  ch0 = (size_t)b*512 + g*256 + mt*128; }
            else if (mt < 4) { dst = kb2; ch0 = (size_t)b*512 + g*256 + (mt-2)*128; }
            else             { dst = vb;  ch0 = (size_t)b*256 + g*128; }
            #pragma unroll
            for (int mi = 0; mi < 2; mi++) {
                int r0 = mb + mi*16 + (lane >> 2);
                float bias0 = bp[g*640 + mt*128 + r0];
                float bias1 = bp[g*640 + mt*128 + r0 + 8];
                uint32_t* row0 = dst + (ch0 + r0)     * HWSZ + pbase;
                uint32_t* row1 = dst + (ch0 + r0 + 8) * HWSZ + pbase;
                #pragma unroll
                for (int nj = 0; nj < 4; nj++) {
                    int col = nb + nj*8 + (lane & 3)*2;
                    uint2 o0 = { pack_h(d[mi][nj][0] + bias0), pack_h(d[mi][nj][1] + bias0) };
                    uint2 o1 = { pack_h(d[mi][nj][2] + bias1), pack_h(d[mi][nj][3] + bias1) };
                    *(uint2*)(row0 + col) = o0;
                    *(uint2*)(row1 + col) = o1;
                }
            }
        }
    }
}

// ---------------- 128x128 transpose per slice (4-byte elements) ----------------
__global__ void transpose_kernel(const float* __restrict__ in, float* __restrict__ out) {
    __shared__ float t[32][33];
    int tile = blockIdx.x;
    int bx = (tile & 3) * 32, by = (tile >> 2) * 32;
    const float* ip = in  + (size_t)blockIdx.y * HWSZ;
    float*       op = out + (size_t)blockIdx.y * HWSZ;
    int x = threadIdx.x, y = threadIdx.y;
    #pragma unroll
    for (int r = 0; r < 32; r += 8)
        t[y+r][x] = ip[(size_t)(by + y + r)*128 + bx + x];
    __syncthreads();
    #pragma unroll
    for (int r = 0; r < 32; r += 8)
        op[(size_t)(bx + y + r)*128 + by + x] = t[x][y+r];
}

// ---------------- axial attention: fp16 2-term, 64 q/CTA, 2 CTAs/SM, fused BN -----
// phase1: S = Qh^T (Kh + Kl);  phase2: O = Vh (Ah + Al)
__global__ __launch_bounds__(256, 2)
void attn_mma_kernel(const uint32_t* __restrict__ qp, const uint32_t* __restrict__ kp,
                     const uint32_t* __restrict__ vp, float* __restrict__ out,
                     float* __restrict__ bns) {
    extern __shared__ char smc[];
    uint32_t sb = smem_u32(smc);
    const uint32_t SQh = 0, SQl = 18432, SKh = 36864, SKl = 71680;
    float* redM = (float*)(smc + 106496);
    float* redS = (float*)(smc + 107520);
    const float SC2 = 0.08838834764831845f * 1.4426950408889634f;  // scale*log2e

    int r = blockIdx.x;
    int n = blockIdx.y >> 1, half = blockIdx.y & 1;
    int b = blockIdx.z;
    size_t qoff = ((size_t)(b*4 + n) * 128) * HWSZ + (size_t)r * 128;
    size_t voff = ((size_t)(b*4 + n) *  64) * HWSZ + (size_t)r * 128;
    int ibq = half * 64;
    int tid = threadIdx.x;
    int lane = tid & 31, wid = tid >> 5;
    int g = lane >> 2, t = lane & 3;

    {
        const uint32_t* qs = qp + qoff + ibq;
        #pragma unroll
        for (int u = 0; u < 8; u++) {
            int idx = u*256 + tid;
            int row = idx >> 4, p4 = (idx & 15) << 2;
            uint32_t off = (uint32_t)(row*144 + p4*2);
            uint4 dq = *(const uint4*)(qs + (size_t)row*HWSZ + p4);
            uint2 qh = { (dq.x & 0xffffu) | (dq.y << 16), (dq.z & 0xffffu) | (dq.w << 16) };
            *(uint2*)(smc + SQh + off) = qh;     // hi only (lo dropped, 2-term)
        }
        const uint32_t* ks2 = kp + qoff;
        #pragma unroll
        for (int u = 0; u < 16; u++) {
            int idx = u*256 + tid;
            int row = idx >> 5, p4 = (idx & 31) << 2;
            uint32_t off = (uint32_t)(row*272 + p4*2);
            uint4 dk = *(const uint4*)(ks2 + (size_t)row*HWSZ + p4);
            uint2 kh = { (dk.x & 0xffffu) | (dk.y << 16), (dk.z & 0xffffu) | (dk.w << 16) };
            uint2 kl = { (dk.x >> 16) | (dk.y & 0xffff0000u), (dk.z >> 16) | (dk.w & 0xffff0000u) };
            *(uint2*)(smc + SKh + off) = kh;
            *(uint2*)(smc + SKl + off) = kl;
        }
    }
    __syncthreads();

    int wm = wid >> 2, wn = wid & 3;
    int m0 = wm * 32, n0 = wn * 32;
    float acc[2][4][4];
    #pragma unroll
    for (int mi = 0; mi < 2; mi++)
        #pragma unroll
        for (int nj = 0; nj < 4; nj++)
            #pragma unroll
            for (int c = 0; c < 4; c++) acc[mi][nj][c] = 0.f;

    int a_r = ((lane >> 4) << 3) + (lane & 7);
    int a_c = ((lane >> 3) & 1) << 3;
    int b_r = (((lane >> 3) & 1) << 3) + (lane & 7);
    int b_c = (lane >> 4) << 3;
    uint32_t aoff0 = (uint32_t)(a_r*144 + (m0 + a_c)*2);
    uint32_t boff0 = (uint32_t)(b_r*272 + (n0 + b_c)*2);

    #pragma unroll
    for (int ks = 0; ks < 8; ks++) {
        uint32_t kq = (uint32_t)(ks * 16 * 144);
        uint32_t kk2 = (uint32_t)(ks * 16 * 272);
        uint32_t aqh[2][4];
        #pragma unroll
        for (int mi = 0; mi < 2; mi++) {
            uint32_t ad = sb + kq + aoff0 + mi*32;
            LDSM_X4_T(aqh[mi][0], aqh[mi][1], aqh[mi][2], aqh[mi][3], ad + SQh);
        }
        uint32_t bkh[2][4], bkl[2][4];
        #pragma unroll
        for (int p = 0; p < 2; p++) {
            uint32_t bd = sb + kk2 + boff0 + p*32;
            LDSM_X4_T(bkh[p][0], bkh[p][1], bkh[p][2], bkh[p][3], bd + SKh);
            LDSM_X4_T(bkl[p][0], bkl[p][1], bkl[p][2], bkl[p][3], bd + SKl);
        }
        #pragma unroll
        for (int mi = 0; mi < 2; mi++)
            #pragma unroll
            for (int nj = 0; nj < 4; nj++) {
                int p = nj >> 1, q2 = (nj & 1) * 2;
                mma16816h(acc[mi][nj], aqh[mi], bkh[p][q2], bkh[p][q2+1]);
                mma16816h(acc[mi][nj], aqh[mi], bkl[p][q2], bkl[p][q2+1]);
            }
    }

    #pragma unroll
    for (int mi = 0; mi < 2; mi++) {
        int rA = m0 + mi*16 + g, rB = rA + 8;
        float mA = -1e30f, mB = -1e30f;
        #pragma unroll
        for (int nj = 0; nj < 4; nj++) {
            mA = fmaxf(mA, fmaxf(acc[mi][nj][0], acc[mi][nj][1]));
            mB = fmaxf(mB, fmaxf(acc[mi][nj][2], acc[mi][nj][3]));
        }
        mA = fmaxf(mA, __shfl_xor_sync(0xffffffffu, mA, 1));
        mA = fmaxf(mA, __shfl_xor_sync(0xffffffffu, mA, 2));
        mB = fmaxf(mB, __shfl_xor_sync(0xffffffffu, mB, 1));
        mB = fmaxf(mB, __shfl_xor_sync(0xffffffffu, mB, 2));
        if (t == 0) { redM[rA*4 + wn] = mA; redM[rB*4 + wn] = mB; }
    }
    __syncthreads();
    #pragma unroll
    for (int mi = 0; mi < 2; mi++) {
        int rA = m0 + mi*16 + g, rB = rA + 8;
        float mxA = fmaxf(fmaxf(redM[rA*4], redM[rA*4+1]), fmaxf(redM[rA*4+2], redM[rA*4+3])) * SC2;
        float mxB = fmaxf(fmaxf(redM[rB*4], redM[rB*4+1]), fmaxf(redM[rB*4+2], redM[rB*4+3])) * SC2;
        float sA = 0.f, sB = 0.f;
        #pragma unroll
        for (int nj = 0; nj < 4; nj++) {
            float e0 = exp2f(fmaf(acc[mi][nj][0], SC2, -mxA));
            float e1 = exp2f(fmaf(acc[mi][nj][1], SC2, -mxA));
            float e2 = exp2f(fmaf(acc[mi][nj][2], SC2, -mxB));
            float e3 = exp2f(fmaf(acc[mi][nj][3], SC2, -mxB));
            acc[mi][nj][0] = e0; acc[mi][nj][1] = e1;
            acc[mi][nj][2] = e2; acc[mi][nj][3] = e3;
            sA += e0 + e1; sB += e2 + e3;
        }
        sA += __shfl_xor_sync(0xffffffffu, sA, 1);
        sA += __shfl_xor_sync(0xffffffffu, sA, 2);
        sB += __shfl_xor_sync(0xffffffffu, sB, 1);
        sB += __shfl_xor_sync(0xffffffffu, sB, 2);
        if (t == 0) { redS[rA*4 + wn] = sA; redS[rB*4 + wn] = sB; }
    }
    __syncthreads();

    #pragma unroll
    for (int mi = 0; mi < 2; mi++) {
        int rA = m0 + mi*16 + g, rB = rA + 8;
        float iA = 1.0f / (redS[rA*4] + redS[rA*4+1] + redS[rA*4+2] + redS[rA*4+3]);
        float iB = 1.0f / (redS[rB*4] + redS[rB*4+1] + redS[rB*4+2] + redS[rB*4+3]);
        #pragma unroll
        for (int nj = 0; nj < 4; nj++) {
            int j0 = n0 + nj*8 + t*2;
            uint32_t h, l;
            split2h(acc[mi][nj][0]*iA, acc[mi][nj][1]*iA, h, l);
            *(uint32_t*)(smc + SQh + rA*272 + j0*2) = h;
            *(uint32_t*)(smc + SQl + rA*272 + j0*2) = l;
            split2h(acc[mi][nj][2]*iB, acc[mi][nj][3]*iB, h, l);
            *(uint32_t*)(smc + SQh + rB*272 + j0*2) = h;
            *(uint32_t*)(smc + SQl + rB*272 + j0*2) = l;
        }
    }
    __syncthreads();

    {
        const uint32_t* vs = vp + voff;
        #pragma unroll
        for (int u = 0; u < 8; u++) {
            int idx = u*256 + tid;
            int row = idx >> 5, p4 = (idx & 31) << 2;
            uint32_t off = (uint32_t)(row*272 + p4*2);
            uint4 dv = *(const uint4*)(vs + (size_t)row*HWSZ + p4);
            uint2 vh = { (dv.x & 0xffffu) | (dv.y << 16), (dv.z & 0xffffu) | (dv.w << 16) };
            *(uint2*)(smc + SKh + off) = vh;     // hi only (Vl dropped, 2-term)
        }
    }
    __syncthreads();

    int c0 = (wid & 3) * 16, i0 = (wid >> 2) * 32;
    float oacc[4][4];
    #pragma unroll
    for (int nj = 0; nj < 4; nj++)
        #pragma unroll
        for (int c = 0; c < 4; c++) oacc[nj][c] = 0.f;

    int ar2 = (((lane >> 3) & 1) << 3) + (lane & 7);
    int ac2 = (lane >> 4) << 3;
    int br2 = ((lane >> 4) << 3) + (lane & 7);
    int bc2 = ((lane >> 3) & 1) << 3;

    #pragma unroll
    for (int ks = 0; ks < 8; ks++) {
        int kb = ks * 16;
        uint32_t avh[4];
        {
            uint32_t ad = sb + (uint32_t)((c0 + ar2)*272 + (kb + ac2)*2);
            LDSM_X4(avh[0], avh[1], avh[2], avh[3], ad + SKh);
        }
        uint32_t bah[2][4], bal[2][4];
        #pragma unroll
        for (int ib2 = 0; ib2 < 2; ib2++) {
            uint32_t bd = sb + (uint32_t)((i0 + ib2*16 + br2)*272 + (kb + bc2)*2);
            LDSM_X4(bah[ib2][0], bah[ib2][1], bah[ib2][2], bah[ib2][3], bd + SQh);
            LDSM_X4(bal[ib2][0], bal[ib2][1], bal[ib2][2], bal[ib2][3], bd + SQl);
        }
        #pragma unroll
        for (int nj = 0; nj < 4; nj++) {
            int ib2 = nj >> 1, q2 = (nj & 1) * 2;
            mma16816h(oacc[nj], avh, bah[ib2][q2], bah[ib2][q2+1]);
            mma16816h(oacc[nj], avh, bal[ib2][q2], bal[ib2][q2+1]);
        }
    }

    {
        int cA = c0 + g, cB = cA + 8;
        float* oA = out + voff + (size_t)cA * HWSZ + ibq;
        float* oB = out + voff + (size_t)cB * HWSZ + ibq;
        #pragma unroll
        for (int nj = 0; nj < 4; nj++) {
            int i = i0 + nj*8 + t*2;
            float2 vA = { oacc[nj][0], oacc[nj][1] };
            float2 vB = { oacc[nj][2], oacc[nj][3] };
            *(float2*)(oA + i) = vA;
            *(float2*)(oB + i) = vB;
        }
    }

    if (n < 2) {
        float s0 = 0.f, q0 = 0.f, s1 = 0.f, q1 = 0.f;
        #pragma unroll
        for (int nj = 0; nj < 4; nj++) {
            s0 += oacc[nj][0] + oacc[nj][1];
            q0 += oacc[nj][0]*oacc[nj][0] + oacc[nj][1]*oacc[nj][1];
            s1 += oacc[nj][2] + oacc[nj][3];
            q1 += oacc[nj][2]*oacc[nj][2] + oacc[nj][3]*oacc[nj][3];
        }
        s0 += __shfl_xor_sync(0xffffffffu, s0, 1);
        s0 += __shfl_xor_sync(0xffffffffu, s0, 2);
        q0 += __shfl_xor_sync(0xffffffffu, q0, 1);
        q0 += __shfl_xor_sync(0xffffffffu, q0, 2);
        s1 += __shfl_xor_sync(0xffffffffu, s1, 1);
        s1 += __shfl_xor_sync(0xffffffffu, s1, 2);
        q1 += __shfl_xor_sync(0xffffffffu, q1, 1);
        q1 += __shfl_xor_sync(0xffffffffu, q1, 2);
        if (t == 0) {
            int chA = n*64 + c0 + g, chB = chA + 8;
            atomicAdd(&bns[chA], s0);       atomicAdd(&bns[256 + chA], q0);
            atomicAdd(&bns[chB], s1);       atomicAdd(&bns[256 + chB], q1);
        }
    }
}

// ---------------- BN finalize ----------------
__global__ void bn_finalize_kernel(const float* __restrict__ bnsW, const float* __restrict__ bnsH,
                                   const float* __restrict__ bnh_w, const float* __restrict__ bnh_b,
                                   const float* __restrict__ bnw_w, const float* __restrict__ bnw_b,
                                   float* __restrict__ scH, float* __restrict__ scW) {
    int tid = threadIdx.x;
    const float N = 65536.0f;
    if (tid < 128) {
        float mean = bnsW[tid] / N;
        float var  = bnsW[256 + tid] / N - mean*mean;
        float scale = bnw_w[tid] * rsqrtf(var + 1e-5f);
        scW[tid] = scale;
        scW[128 + tid] = bnw_b[tid] - mean*scale;
    } else {
        int c = tid - 128;
        float mean = bnsH[c] / N;
        float var  = bnsH[256 + c] / N - mean*mean;
        float scale = bnh_w[c] * rsqrtf(var + 1e-5f);
        scH[c] = scale;
        scH[128 + c] = bnh_b[c] - mean*scale;
    }
}

// ---------------- fused epilogue (reads oHT transposed in-kernel) ----------------
__global__ void final_fused_kernel(const float* __restrict__ x, const float* __restrict__ oht,
                                   const float* __restrict__ ow, const float* __restrict__ scH,
                                   const float* __restrict__ scW, const float* __restrict__ gamma,
                                   float* __restrict__ out) {
    __shared__ float t[32][33];
    int tile = blockIdx.x;
    int h0 = (tile >> 2) * 32, w0 = (tile & 3) * 32;
    int c = blockIdx.y, b = blockIdx.z;
    int tx = threadIdx.x, ty = threadIdx.y;
    float gm = gamma[0];

    const float* ohs = oht + (size_t)(b*256 + c) * HWSZ;
    #pragma unroll
    for (int r = 0; r < 32; r += 8)
        t[ty + r][tx] = ohs[(size_t)(w0 + ty + r)*128 + h0 + tx];
    __syncthreads();

    const float* ows = ow + (size_t)(b*256 + c) * HWSZ;
    const float* x0p = x + (size_t)(b*512 + c)       * HWSZ;
    const float* x1p = x + (size_t)(b*512 + c + 256) * HWSZ;
    float* o0p = out + (size_t)(b*512 + c)       * HWSZ;
    float* o1p = out + (size_t)(b*512 + c + 256) * HWSZ;
    bool dop = (c < 128);
    float sH = 0.f, shH = 0.f, sW = 0.f, shW = 0.f;
    if (dop) { sH = scH[c]; shH = scH[128+c]; sW = scW[c]; shW = scW[128+c]; }
    float* p0p = out + 33554432ull + (size_t)(b*128 + c) * HWSZ;
    float* p1p = out + 41943040ull + (size_t)(b*128 + c) * HWSZ;

    #pragma unroll
    for (int r = 0; r < 32; r += 8) {
        int hr = ty + r;
        size_t pix = (size_t)(h0 + hr)*128 + w0 + tx;
        float hv = t[tx][hr];
        float wv = ows[pix];
        o0p[pix] = gm*fmaxf(hv, 0.f) + x0p[pix];
        o1p[pix] = gm*fmaxf(wv, 0.f) + x1p[pix];
        if (dop) {
            p0p[pix] = hv*sH + shH;
            p1p[pix] = wv*sW + shW;
        }
    }
}

// ---------------- launch (single stream) ----------------
extern "C" void kernel_launch(void* const* d_in, const int* in_sizes, int n_in,
                              void* d_out, int out_size) {
    const float* x     = (const float*)d_in[0];
    const float* wq    = (const float*)d_in[1];
    const float* bq    = (const float*)d_in[2];
    const float* wk    = (const float*)d_in[3];
    const float* bk    = (const float*)d_in[4];
    const float* wv    = (const float*)d_in[5];
    const float* bv    = (const float*)d_in[6];
    const float* bnh_w = (const float*)d_in[7];
    const float* bnh_b = (const float*)d_in[8];
    const float* bnw_w = (const float*)d_in[9];
    const float* bnw_b = (const float*)d_in[10];
    const float* gamma = (const float*)d_in[11];
    float* out = (float*)d_out;

    uint32_t *qp, *kp, *vp, *qpT, *kpT, *vpT;
    float *oW, *oHT, *scH, *scW, *bp, *bnsW, *bnsH;
    __half *wph;
    cudaGetSymbolAddress((void**)&qp,   g_qp);
    cudaGetSymbolAddress((void**)&kp,   g_kp);
    cudaGetSymbolAddress((void**)&vp,   g_vp);
    cudaGetSymbolAddress((void**)&qpT,  g_qpT);
    cudaGetSymbolAddress((void**)&kpT,  g_kpT);
    cudaGetSymbolAddress((void**)&vpT,  g_vpT);
    cudaGetSymbolAddress((void**)&oW,   g_outW);
    cudaGetSymbolAddress((void**)&oHT,  g_outHT);
    cudaGetSymbolAddress((void**)&scH,  g_scH);
    cudaGetSymbolAddress((void**)&scW,  g_scW);
    cudaGetSymbolAddress((void**)&bnsW, g_bnsW);
    cudaGetSymbolAddress((void**)&bnsH, g_bnsH);
    cudaGetSymbolAddress((void**)&wph,  g_wph);
    cudaGetSymbolAddress((void**)&bp,   g_bp);

    cudaFuncSetAttribute(gemm_kernel, cudaFuncAttributeMaxDynamicSharedMemorySize, GEMM_SMEM);
    cudaFuncSetAttribute(attn_mma_kernel, cudaFuncAttributeMaxDynamicSharedMemorySize, ATT3_SMEM);

    cudaMemsetAsync(bnsW, 0, 512 * sizeof(float));
    cudaMemsetAsync(bnsH, 0, 512 * sizeof(float));

    prepw_one<<<512, 256>>>(wq, bq, wph, bp, 0,   256);
    prepw_one<<<512, 256>>>(wk, bk, wph, bp, 256, 256);
    prepw_one<<<256, 256>>>(wv, bv, wph, bp, 512, 128);
    // #6 (profiled): GEMM — fp16 2-term, 256 threads, 64 px, 2 CTAs/SM
    gemm_kernel<<<dim3(256, 8), 256, GEMM_SMEM>>>(x, wph, bp, qp, kp, vp);

    attn_mma_kernel<<<dim3(128, 8, 4), 256, ATT3_SMEM>>>(qp,  kp,  vp,  oW,  bnsW);
    transpose_kernel<<<dim3(16, 2048), dim3(32,8)>>>((const float*)qp, (float*)qpT);
    transpose_kernel<<<dim3(16, 2048), dim3(32,8)>>>((const float*)kp, (float*)kpT);
    transpose_kernel<<<dim3(16, 1024), dim3(32,8)>>>((const float*)vp, (float*)vpT);
    attn_mma_kernel<<<dim3(128, 8, 4), 256, ATT3_SMEM>>>(qpT, kpT, vpT, oHT, bnsH);

    bn_finalize_kernel<<<1, 256>>>(bnsW, bnsH, bnh_w, bnh_b, bnw_w, bnw_b, scH, scW);
    final_fused_kernel<<<dim3(16, 256, 4), dim3(32, 8)>>>(x, oHT, oW, scH, scW, gamma, out);
}

// round 16
// speedup vs baseline: 1.6832x; 1.0015x over previous
#include <cuda_runtime.h>
#include <cuda_fp16.h>
#include <math.h>
#include <stdint.h>

#define HWSZ 16384
#define GEMM_SMEM 91136
#define ATT3_SMEM 108544

// ---------------- scratch ----------------
__device__ uint32_t g_qp [4ull*512*16384];   // packed fp16: hi | lo<<16
__device__ uint32_t g_kp [4ull*512*16384];
__device__ uint32_t g_vp [4ull*256*16384];
__device__ uint32_t g_qpT[4ull*512*16384];
__device__ uint32_t g_kpT[4ull*512*16384];
__device__ uint32_t g_vpT[4ull*256*16384];
__device__ float g_outW [4ull*256*16384];
__device__ float g_outHT[4ull*256*16384];
__device__ float g_scH[256];
__device__ float g_scW[256];
__device__ float g_bnsW[512];   // [0..255]=sum, [256..511]=sumsq
__device__ float g_bnsH[512];
__device__ __half g_wph[2*640*256];          // [g][m][k], fp16 hi only
__device__ float g_bp[2*640];

// ---------------- helpers ----------------
__device__ __forceinline__ uint32_t smem_u32(const void* p) {
    uint32_t a;
    asm("{ .reg .u64 t; cvta.to.shared.u64 t, %1; cvt.u32.u64 %0, t; }" : "=r"(a) : "l"(p));
    return a;
}
#define LDSM_X4(r0, r1, r2, r3, addr) \
    asm volatile("ldmatrix.sync.aligned.m8n8.x4.shared.b16 {%0,%1,%2,%3}, [%4];" \
        : "=r"(r0), "=r"(r1), "=r"(r2), "=r"(r3) : "r"(addr))
#define LDSM_X4_T(r0, r1, r2, r3, addr) \
    asm volatile("ldmatrix.sync.aligned.m8n8.x4.trans.shared.b16 {%0,%1,%2,%3}, [%4];" \
        : "=r"(r0), "=r"(r1), "=r"(r2), "=r"(r3) : "r"(addr))
#define CP_ASYNC16(dst, src) \
    asm volatile("cp.async.cg.shared.global [%0], [%1], 16;" :: "r"(dst), "l"(src))
#define CP_COMMIT() asm volatile("cp.async.commit_group;" ::: "memory")
#define CP_WAIT0()  asm volatile("cp.async.wait_group 0;" ::: "memory")

// fp16 x fp16 -> f32 accumulate
__device__ __forceinline__ void mma16816h(float* d, const uint32_t* a,
                                          uint32_t b0, uint32_t b1) {
    asm volatile(
        "mma.sync.aligned.m16n8k16.row.col.f32.f16.f16.f32 "
        "{%0,%1,%2,%3}, {%4,%5,%6,%7}, {%8,%9}, {%0,%1,%2,%3};"
        : "+f"(d[0]), "+f"(d[1]), "+f"(d[2]), "+f"(d[3])
        : "r"(a[0]), "r"(a[1]), "r"(a[2]), "r"(a[3]), "r"(b0), "r"(b1));
}
__device__ __forceinline__ uint32_t pack_h(float f) {
    __half h = __float2half_rn(f);
    __half l = __float2half_rn(f - __half2float(h));
    return (uint32_t)__half_as_ushort(h) | ((uint32_t)__half_as_ushort(l) << 16);
}
__device__ __forceinline__ void split2h(float a, float b, uint32_t& h, uint32_t& l) {
    __half ha = __float2half_rn(a);
    __half hb = __float2half_rn(b);
    __half la = __float2half_rn(a - __half2float(ha));
    __half lb = __float2half_rn(b - __half2float(hb));
    h = (uint32_t)__half_as_ushort(ha) | ((uint32_t)__half_as_ushort(hb) << 16);
    l = (uint32_t)__half_as_ushort(la) | ((uint32_t)__half_as_ushort(lb) << 16);
}
__device__ __forceinline__ void cvt4h(float4 v, uint2& h, uint2& l) {
    split2h(v.x, v.y, h.x, l.x);
    split2h(v.z, v.w, h.y, l.y);
}
// A chunk layout: 128 rows x 32 k fp16; row stride 64B, XOR swizzle on 16B segs
__device__ __forceinline__ uint32_t a32_addr(uint32_t tbase, int row, int kc) {
    return tbase + (uint32_t)((row << 6) + (((kc & 31) << 1) ^ (((row >> 1) & 3) << 4)));
}

// ---------------- weight pack (fp16 hi only) ----------------
__global__ void prepw_one(const float* __restrict__ w, const float* __restrict__ bias,
                          __half* __restrict__ wph, float* __restrict__ bp,
                          int m_off, int M) {
    int idx = blockIdx.x * 256 + threadIdx.x;
    int per_g = M * 256;
    int g = idx / per_g;
    int r = idx - g * per_g;
    int m = r >> 8, k = r & 255;
    float wv = w[(size_t)(g*M + m) * 256 + k];
    size_t didx = (size_t)(g*640 + m_off + m) * 256 + k;
    wph[didx] = __float2half_rn(wv);
    if (k == 0) bp[g*640 + m_off + m] = bias[g*M + m];
}

// ---- stage [128 x 32] fp16 A chunk into swizzled layout, async (256 threads) ----
__device__ __forceinline__ void stage_a32(uint32_t smb, const __half* __restrict__ src,
                                          int tid) {
    #pragma unroll
    for (int it = 0; it < 2; it++) {
        int idx = it * 256 + tid;          // 0..511
        int row = idx >> 2;
        int k8 = (idx & 3) << 3;
        uint32_t byte = (uint32_t)((row << 6) + ((k8 << 1) ^ (((row >> 1) & 3) << 4)));
        CP_ASYNC16(smb + byte, src + (size_t)row * 256 + k8);
    }
}

// ---------------- fused qkv projection GEMM: fp16 2-term, 2 CTAs/SM ---------------
// D = Wh * (Xh + Xl);  A operand = Wh only (8KB ping-pong), B = x hi/lo resident
__global__ __launch_bounds__(256, 2)
void gemm_kernel(const float* __restrict__ x,
                 const __half* __restrict__ wph, const float* __restrict__ bp,
                 uint32_t* __restrict__ qb, uint32_t* __restrict__ kb2, uint32_t* __restrict__ vb) {
    extern __shared__ char sm[];
    uint32_t sbase = smem_u32(sm);
    const uint32_t AHb[2] = {1024, 9216};
    const uint32_t BH = 17408, BL = 54272;   // each 256 rows x 144B = 36864B, ends 91136
    int tid = threadIdx.x;
    int lane = tid & 31, wid = tid >> 5;
    int pbase = blockIdx.x * 64;
    int z = blockIdx.y;                 // b*2+g
    int b = z >> 1, g = z & 1;
    const __half* wbase_h = wph + (size_t)g*640*256;

    // prefetch A chunk 0 (m-tile 0, k 0..31)
    stage_a32(sbase + AHb[0], wbase_h, tid);
    CP_COMMIT();

    // stage B: x [k=256][64 px] f32 -> fp16 hi/lo, rows stride 144B
    {
        const float* xb = x + ((size_t)b*512 + g*256) * HWSZ + pbase;
        #pragma unroll 4
        for (int it = 0; it < 16; it++) {
            int idx = it * 256 + tid;       // 0..4095 float4
            int row = idx >> 4;
            int p4  = (idx & 15) << 2;
            float4 v = *(const float4*)(xb + (size_t)row * HWSZ + p4);
            uint2 h, l;
            cvt4h(v, h, l);
            uint32_t off = (uint32_t)(row * 144 + p4 * 2);
            *(uint2*)(sm + BH + off) = h;
            *(uint2*)(sm + BL + off) = l;
        }
    }

    int mb = (wid & 3) * 32;            // warp M offset (4 slots of 32 ch)
    int nb = (wid >> 2) * 32;           // warp N offset (2 slots of 32 px)
    int laneA_row = ((lane >> 3) & 1) * 8 + (lane & 7);
    int laneA_k8  = (lane >> 4) * 8;
    int bt_r = (((lane >> 3) & 1) << 3) + (lane & 7);
    int bt_c = (lane >> 4) << 3;

    float d[2][4][4];

    #pragma unroll 1
    for (int q = 0; q < 40; q++) {      // mt = q>>3, 32-k chunk = q&7
        int mt = q >> 3;
        if ((q & 7) == 0) {
            #pragma unroll
            for (int mi = 0; mi < 2; mi++)
                #pragma unroll
                for (int nj = 0; nj < 4; nj++)
                    #pragma unroll
                    for (int c = 0; c < 4; c++) d[mi][nj][c] = 0.f;
        }
        CP_WAIT0();
        __syncthreads();
        if (q < 39) {
            int qq = q + 1;
            size_t aoff = ((size_t)(qq >> 3) * 128) * 256 + (qq & 7) * 32;
            stage_a32(sbase + AHb[qq & 1], wbase_h + aoff, tid);
            CP_COMMIT();
        }

        uint32_t AH = sbase + AHb[q & 1];
        int kbase = (q & 7) * 32;       // B global k offset

        #pragma unroll
        for (int ks = 0; ks < 2; ks++) {
            int kl = ks * 16;
            int kk = kbase + kl;
            uint32_t aH[2][4];
            #pragma unroll
            for (int mi = 0; mi < 2; mi++)
                LDSM_X4(aH[mi][0], aH[mi][1], aH[mi][2], aH[mi][3],
                        a32_addr(AH, mb + mi*16 + laneA_row, kl + laneA_k8));
            uint32_t bHf[2][4], bLf[2][4];
            #pragma unroll
            for (int p = 0; p < 2; p++) {
                uint32_t bd = sbase + (uint32_t)((kk + bt_r)*144 + (nb + p*16 + bt_c)*2);
                LDSM_X4_T(bHf[p][0], bHf[p][1], bHf[p][2], bHf[p][3], bd + BH);
                LDSM_X4_T(bLf[p][0], bLf[p][1], bLf[p][2], bLf[p][3], bd + BL);
            }
            #pragma unroll
            for (int mi = 0; mi < 2; mi++)
                #pragma unroll
                for (int nj = 0; nj < 4; nj++) {
                    int p = nj >> 1, qx = (nj & 1) * 2;
                    mma16816h(d[mi][nj], aH[mi], bHf[p][qx], bHf[p][qx+1]);
                    mma16816h(d[mi][nj], aH[mi], bLf[p][qx], bLf[p][qx+1]);
                }
        }

        if ((q & 7) == 7) {
            uint32_t* dst; size_t ch0;
            if (mt < 2)      { dst = qb;  ch0 = (size_t)b*512 + g*256 + mt*128; }
            else if (mt < 4) { dst = kb2; ch0 = (size_t)b*512 + g*256 + (mt-2)*128; }
            else             { dst = vb;  ch0 = (size_t)b*256 + g*128; }
            #pragma unroll
            for (int mi = 0; mi < 2; mi++) {
                int r0 = mb + mi*16 + (lane >> 2);
                float bias0 = bp[g*640 + mt*128 + r0];
                float bias1 = bp[g*640 + mt*128 + r0 + 8];
                uint32_t* row0 = dst + (ch0 + r0)     * HWSZ + pbase;
                uint32_t* row1 = dst + (ch0 + r0 + 8) * HWSZ + pbase;
                #pragma unroll
                for (int nj = 0; nj < 4; nj++) {
                    int col = nb + nj*8 + (lane & 3)*2;
                    uint2 o0 = { pack_h(d[mi][nj][0] + bias0), pack_h(d[mi][nj][1] + bias0) };
                    uint2 o1 = { pack_h(d[mi][nj][2] + bias1), pack_h(d[mi][nj][3] + bias1) };
                    *(uint2*)(row0 + col) = o0;
                    *(uint2*)(row1 + col) = o1;
                }
            }
        }
    }
}

// ---------------- 128x128 transpose per slice (4-byte elements) ----------------
__global__ void transpose_kernel(const float* __restrict__ in, float* __restrict__ out) {
    __shared__ float t[32][33];
    int tile = blockIdx.x;
    int bx = (tile & 3) * 32, by = (tile >> 2) * 32;
    const float* ip = in  + (size_t)blockIdx.y * HWSZ;
    float*       op = out + (size_t)blockIdx.y * HWSZ;
    int x = threadIdx.x, y = threadIdx.y;
    #pragma unroll
    for (int r = 0; r < 32; r += 8)
        t[y+r][x] = ip[(size_t)(by + y + r)*128 + bx + x];
    __syncthreads();
    #pragma unroll
    for (int r = 0; r < 32; r += 8)
        op[(size_t)(bx + y + r)*128 + by + x] = t[x][y+r];
}

// ---------------- axial attention: fp16 2-term, 64 q/CTA, 2 CTAs/SM, fused BN -----
// phase1: S = Qh^T (Kh + Kl);  phase2: O = Vh (Ah + Al)
__global__ __launch_bounds__(256, 2)
void attn_mma_kernel(const uint32_t* __restrict__ qp, const uint32_t* __restrict__ kp,
                     const uint32_t* __restrict__ vp, float* __restrict__ out,
                     float* __restrict__ bns) {
    extern __shared__ char smc[];
    uint32_t sb = smem_u32(smc);
    const uint32_t SQh = 0, SQl = 18432, SKh = 36864, SKl = 71680;
    float* redM = (float*)(smc + 106496);
    float* redS = (float*)(smc + 107520);
    const float SC2 = 0.08838834764831845f * 1.4426950408889634f;  // scale*log2e

    int r = blockIdx.x;
    int n = blockIdx.y >> 1, half = blockIdx.y & 1;
    int b = blockIdx.z;
    size_t qoff = ((size_t)(b*4 + n) * 128) * HWSZ + (size_t)r * 128;
    size_t voff = ((size_t)(b*4 + n) *  64) * HWSZ + (size_t)r * 128;
    int ibq = half * 64;
    int tid = threadIdx.x;
    int lane = tid & 31, wid = tid >> 5;
    int g = lane >> 2, t = lane & 3;

    {
        const uint32_t* qs = qp + qoff + ibq;
        #pragma unroll
        for (int u = 0; u < 8; u++) {
            int idx = u*256 + tid;
            int row = idx >> 4, p4 = (idx & 15) << 2;
            uint32_t off = (uint32_t)(row*144 + p4*2);
            uint4 dq = *(const uint4*)(qs + (size_t)row*HWSZ + p4);
            uint2 qh = { (dq.x & 0xffffu) | (dq.y << 16), (dq.z & 0xffffu) | (dq.w << 16) };
            *(uint2*)(smc + SQh + off) = qh;     // hi only (lo dropped, 2-term)
        }
        const uint32_t* ks2 = kp + qoff;
        #pragma unroll
        for (int u = 0; u < 16; u++) {
            int idx = u*256 + tid;
            int row = idx >> 5, p4 = (idx & 31) << 2;
            uint32_t off = (uint32_t)(row*272 + p4*2);
            uint4 dk = *(const uint4*)(ks2 + (size_t)row*HWSZ + p4);
            uint2 kh = { (dk.x & 0xffffu) | (dk.y << 16), (dk.z & 0xffffu) | (dk.w << 16) };
            uint2 kl = { (dk.x >> 16) | (dk.y & 0xffff0000u), (dk.z >> 16) | (dk.w & 0xffff0000u) };
            *(uint2*)(smc + SKh + off) = kh;
            *(uint2*)(smc + SKl + off) = kl;
        }
    }
    __syncthreads();

    int wm = wid >> 2, wn = wid & 3;
    int m0 = wm * 32, n0 = wn * 32;
    float acc[2][4][4];
    #pragma unroll
    for (int mi = 0; mi < 2; mi++)
        #pragma unroll
        for (int nj = 0; nj < 4; nj++)
            #pragma unroll
            for (int c = 0; c < 4; c++) acc[mi][nj][c] = 0.f;

    int a_r = ((lane >> 4) << 3) + (lane & 7);
    int a_c = ((lane >> 3) & 1) << 3;
    int b_r = (((lane >> 3) & 1) << 3) + (lane & 7);
    int b_c = (lane >> 4) << 3;
    uint32_t aoff0 = (uint32_t)(a_r*144 + (m0 + a_c)*2);
    uint32_t boff0 = (uint32_t)(b_r*272 + (n0 + b_c)*2);

    #pragma unroll
    for (int ks = 0; ks < 8; ks++) {
        uint32_t kq = (uint32_t)(ks * 16 * 144);
        uint32_t kk2 = (uint32_t)(ks * 16 * 272);
        uint32_t aqh[2][4];
        #pragma unroll
        for (int mi = 0; mi < 2; mi++) {
            uint32_t ad = sb + kq + aoff0 + mi*32;
            LDSM_X4_T(aqh[mi][0], aqh[mi][1], aqh[mi][2], aqh[mi][3], ad + SQh);
        }
        uint32_t bkh[2][4], bkl[2][4];
        #pragma unroll
        for (int p = 0; p < 2; p++) {
            uint32_t bd = sb + kk2 + boff0 + p*32;
            LDSM_X4_T(bkh[p][0], bkh[p][1], bkh[p][2], bkh[p][3], bd + SKh);
            LDSM_X4_T(bkl[p][0], bkl[p][1], bkl[p][2], bkl[p][3], bd + SKl);
        }
        #pragma unroll
        for (int mi = 0; mi < 2; mi++)
            #pragma unroll
            for (int nj = 0; nj < 4; nj++) {
                int p = nj >> 1, q2 = (nj & 1) * 2;
                mma16816h(acc[mi][nj], aqh[mi], bkh[p][q2], bkh[p][q2+1]);
                mma16816h(acc[mi][nj], aqh[mi], bkl[p][q2], bkl[p][q2+1]);
            }
    }

    #pragma unroll
    for (int mi = 0; mi < 2; mi++) {
        int rA = m0 + mi*16 + g, rB = rA + 8;
        float mA = -1e30f, mB = -1e30f;
        #pragma unroll
        for (int nj = 0; nj < 4; nj++) {
            mA = fmaxf(mA, fmaxf(acc[mi][nj][0], acc[mi][nj][1]));
            mB = fmaxf(mB, fmaxf(acc[mi][nj][2], acc[mi][nj][3]));
        }
        mA = fmaxf(mA, __shfl_xor_sync(0xffffffffu, mA, 1));
        mA = fmaxf(mA, __shfl_xor_sync(0xffffffffu, mA, 2));
        mB = fmaxf(mB, __shfl_xor_sync(0xffffffffu, mB, 1));
        mB = fmaxf(mB, __shfl_xor_sync(0xffffffffu, mB, 2));
        if (t == 0) { redM[rA*4 + wn] = mA; redM[rB*4 + wn] = mB; }
    }
    __syncthreads();
    #pragma unroll
    for (int mi = 0; mi < 2; mi++) {
        int rA = m0 + mi*16 + g, rB = rA + 8;
        float mxA = fmaxf(fmaxf(redM[rA*4], redM[rA*4+1]), fmaxf(redM[rA*4+2], redM[rA*4+3])) * SC2;
        float mxB = fmaxf(fmaxf(redM[rB*4], redM[rB*4+1]), fmaxf(redM[rB*4+2], redM[rB*4+3])) * SC2;
        float sA = 0.f, sB = 0.f;
        #pragma unroll
        for (int nj = 0; nj < 4; nj++) {
            float e0 = exp2f(fmaf(acc[mi][nj][0], SC2, -mxA));
            float e1 = exp2f(fmaf(acc[mi][nj][1], SC2, -mxA));
            float e2 = exp2f(fmaf(acc[mi][nj][2], SC2, -mxB));
            float e3 = exp2f(fmaf(acc[mi][nj][3], SC2, -mxB));
            acc[mi][nj][0] = e0; acc[mi][nj][1] = e1;
            acc[mi][nj][2] = e2; acc[mi][nj][3] = e3;
            sA += e0 + e1; sB += e2 + e3;
        }
        sA += __shfl_xor_sync(0xffffffffu, sA, 1);
        sA += __shfl_xor_sync(0xffffffffu, sA, 2);
        sB += __shfl_xor_sync(0xffffffffu, sB, 1);
        sB += __shfl_xor_sync(0xffffffffu, sB, 2);
        if (t == 0) { redS[rA*4 + wn] = sA; redS[rB*4 + wn] = sB; }
    }
    __syncthreads();

    #pragma unroll
    for (int mi = 0; mi < 2; mi++) {
        int rA = m0 + mi*16 + g, rB = rA + 8;
        float iA = 1.0f / (redS[rA*4] + redS[rA*4+1] + redS[rA*4+2] + redS[rA*4+3]);
        float iB = 1.0f / (redS[rB*4] + redS[rB*4+1] + redS[rB*4+2] + redS[rB*4+3]);
        #pragma unroll
        for (int nj = 0; nj < 4; nj++) {
            int j0 = n0 + nj*8 + t*2;
            uint32_t h, l;
            split2h(acc[mi][nj][0]*iA, acc[mi][nj][1]*iA, h, l);
            *(uint32_t*)(smc + SQh + rA*272 + j0*2) = h;
            *(uint32_t*)(smc + SQl + rA*272 + j0*2) = l;
            split2h(acc[mi][nj][2]*iB, acc[mi][nj][3]*iB, h, l);
            *(uint32_t*)(smc + SQh + rB*272 + j0*2) = h;
            *(uint32_t*)(smc + SQl + rB*272 + j0*2) = l;
        }
    }
    __syncthreads();

    {
        const uint32_t* vs = vp + voff;
        #pragma unroll
        for (int u = 0; u < 8; u++) {
            int idx = u*256 + tid;
            int row = idx >> 5, p4 = (idx & 31) << 2;
            uint32_t off = (uint32_t)(row*272 + p4*2);
            uint4 dv = *(const uint4*)(vs + (size_t)row*HWSZ + p4);
            uint2 vh = { (dv.x & 0xffffu) | (dv.y << 16), (dv.z & 0xffffu) | (dv.w << 16) };
            *(uint2*)(smc + SKh + off) = vh;     // hi only (Vl dropped, 2-term)
        }
    }
    __syncthreads();

    int c0 = (wid & 3) * 16, i0 = (wid >> 2) * 32;
    float oacc[4][4];
    #pragma unroll
    for (int nj = 0; nj < 4; nj++)
        #pragma unroll
        for (int c = 0; c < 4; c++) oacc[nj][c] = 0.f;

    int ar2 = (((lane >> 3) & 1) << 3) + (lane & 7);
    int ac2 = (lane >> 4) << 3;
    int br2 = ((lane >> 4) << 3) + (lane & 7);
    int bc2 = ((lane >> 3) & 1) << 3;

    #pragma unroll
    for (int ks = 0; ks < 8; ks++) {
        int kb = ks * 16;
        uint32_t avh[4];
        {
            uint32_t ad = sb + (uint32_t)((c0 + ar2)*272 + (kb + ac2)*2);
            LDSM_X4(avh[0], avh[1], avh[2], avh[3], ad + SKh);
        }
        uint32_t bah[2][4], bal[2][4];
        #pragma unroll
        for (int ib2 = 0; ib2 < 2; ib2++) {
            uint32_t bd = sb + (uint32_t)((i0 + ib2*16 + br2)*272 + (kb + bc2)*2);
            LDSM_X4(bah[ib2][0], bah[ib2][1], bah[ib2][2], bah[ib2][3], bd + SQh);
            LDSM_X4(bal[ib2][0], bal[ib2][1], bal[ib2][2], bal[ib2][3], bd + SQl);
        }
        #pragma unroll
        for (int nj = 0; nj < 4; nj++) {
            int ib2 = nj >> 1, q2 = (nj & 1) * 2;
            mma16816h(oacc[nj], avh, bah[ib2][q2], bah[ib2][q2+1]);
            mma16816h(oacc[nj], avh, bal[ib2][q2], bal[ib2][q2+1]);
        }
    }

    {
        int cA = c0 + g, cB = cA + 8;
        float* oA = out + voff + (size_t)cA * HWSZ + ibq;
        float* oB = out + voff + (size_t)cB * HWSZ + ibq;
        #pragma unroll
        for (int nj = 0; nj < 4; nj++) {
            int i = i0 + nj*8 + t*2;
            float2 vA = { oacc[nj][0], oacc[nj][1] };
            float2 vB = { oacc[nj][2], oacc[nj][3] };
            *(float2*)(oA + i) = vA;
            *(float2*)(oB + i) = vB;
        }
    }

    if (n < 2) {
        float s0 = 0.f, q0 = 0.f, s1 = 0.f, q1 = 0.f;
        #pragma unroll
        for (int nj = 0; nj < 4; nj++) {
            s0 += oacc[nj][0] + oacc[nj][1];
            q0 += oacc[nj][0]*oacc[nj][0] + oacc[nj][1]*oacc[nj][1];
            s1 += oacc[nj][2] + oacc[nj][3];
            q1 += oacc[nj][2]*oacc[nj][2] + oacc[nj][3]*oacc[nj][3];
        }
        s0 += __shfl_xor_sync(0xffffffffu, s0, 1);
        s0 += __shfl_xor_sync(0xffffffffu, s0, 2);
        q0 += __shfl_xor_sync(0xffffffffu, q0, 1);
        q0 += __shfl_xor_sync(0xffffffffu, q0, 2);
        s1 += __shfl_xor_sync(0xffffffffu, s1, 1);
        s1 += __shfl_xor_sync(0xffffffffu, s1, 2);
        q1 += __shfl_xor_sync(0xffffffffu, q1, 1);
        q1 += __shfl_xor_sync(0xffffffffu, q1, 2);
        if (t == 0) {
            int chA = n*64 + c0 + g, chB = chA + 8;
            atomicAdd(&bns[chA], s0);       atomicAdd(&bns[256 + chA], q0);
            atomicAdd(&bns[chB], s1);       atomicAdd(&bns[256 + chB], q1);
        }
    }
}

// ---------------- BN finalize ----------------
__global__ void bn_finalize_kernel(const float* __restrict__ bnsW, const float* __restrict__ bnsH,
                                   const float* __restrict__ bnh_w, const float* __restrict__ bnh_b,
                                   const float* __restrict__ bnw_w, const float* __restrict__ bnw_b,
                                   float* __restrict__ scH, float* __restrict__ scW) {
    int tid = threadIdx.x;
    const float N = 65536.0f;
    if (tid < 128) {
        float mean = bnsW[tid] / N;
        float var  = bnsW[256 + tid] / N - mean*mean;
        float scale = bnw_w[tid] * rsqrtf(var + 1e-5f);
        scW[tid] = scale;
        scW[128 + tid] = bnw_b[tid] - mean*scale;
    } else {
        int c = tid - 128;
        float mean = bnsH[c] / N;
        float var  = bnsH[256 + c] / N - mean*mean;
        float scale = bnh_w[c] * rsqrtf(var + 1e-5f);
        scH[c] = scale;
        scH[128 + c] = bnh_b[c] - mean*scale;
    }
}

// ---------------- fused epilogue (reads oHT transposed in-kernel) ----------------
__global__ void final_fused_kernel(const float* __restrict__ x, const float* __restrict__ oht,
                                   const float* __restrict__ ow, const float* __restrict__ scH,
                                   const float* __restrict__ scW, const float* __restrict__ gamma,
                                   float* __restrict__ out) {
    __shared__ float t[32][33];
    int tile = blockIdx.x;
    int h0 = (tile >> 2) * 32, w0 = (tile & 3) * 32;
    int c = blockIdx.y, b = blockIdx.z;
    int tx = threadIdx.x, ty = threadIdx.y;
    float gm = gamma[0];

    const float* ohs = oht + (size_t)(b*256 + c) * HWSZ;
    #pragma unroll
    for (int r = 0; r < 32; r += 8)
        t[ty + r][tx] = ohs[(size_t)(w0 + ty + r)*128 + h0 + tx];
    __syncthreads();

    const float* ows = ow + (size_t)(b*256 + c) * HWSZ;
    const float* x0p = x + (size_t)(b*512 + c)       * HWSZ;
    const float* x1p = x + (size_t)(b*512 + c + 256) * HWSZ;
    float* o0p = out + (size_t)(b*512 + c)       * HWSZ;
    float* o1p = out + (size_t)(b*512 + c + 256) * HWSZ;
    bool dop = (c < 128);
    float sH = 0.f, shH = 0.f, sW = 0.f, shW = 0.f;
    if (dop) { sH = scH[c]; shH = scH[128+c]; sW = scW[c]; shW = scW[128+c]; }
    float* p0p = out + 33554432ull + (size_t)(b*128 + c) * HWSZ;
    float* p1p = out + 41943040ull + (size_t)(b*128 + c) * HWSZ;

    #pragma unroll
    for (int r = 0; r < 32; r += 8) {
        int hr = ty + r;
        size_t pix = (size_t)(h0 + hr)*128 + w0 + tx;
        float hv = t[tx][hr];
        float wv = ows[pix];
        o0p[pix] = gm*fmaxf(hv, 0.f) + x0p[pix];
        o1p[pix] = gm*fmaxf(wv, 0.f) + x1p[pix];
        if (dop) {
            p0p[pix] = hv*sH + shH;
            p1p[pix] = wv*sW + shW;
        }
    }
}

// ---------------- launch (single stream) ----------------
extern "C" void kernel_launch(void* const* d_in, const int* in_sizes, int n_in,
                              void* d_out, int out_size) {
    const float* x     = (const float*)d_in[0];
    const float* wq    = (const float*)d_in[1];
    const float* bq    = (const float*)d_in[2];
    const float* wk    = (const float*)d_in[3];
    const float* bk    = (const float*)d_in[4];
    const float* wv    = (const float*)d_in[5];
    const float* bv    = (const float*)d_in[6];
    const float* bnh_w = (const float*)d_in[7];
    const float* bnh_b = (const float*)d_in[8];
    const float* bnw_w = (const float*)d_in[9];
    const float* bnw_b = (const float*)d_in[10];
    const float* gamma = (const float*)d_in[11];
    float* out = (float*)d_out;

    uint32_t *qp, *kp, *vp, *qpT, *kpT, *vpT;
    float *oW, *oHT, *scH, *scW, *bp, *bnsW, *bnsH;
    __half *wph;
    cudaGetSymbolAddress((void**)&qp,   g_qp);
    cudaGetSymbolAddress((void**)&kp,   g_kp);
    cudaGetSymbolAddress((void**)&vp,   g_vp);
    cudaGetSymbolAddress((void**)&qpT,  g_qpT);
    cudaGetSymbolAddress((void**)&kpT,  g_kpT);
    cudaGetSymbolAddress((void**)&vpT,  g_vpT);
    cudaGetSymbolAddress((void**)&oW,   g_outW);
    cudaGetSymbolAddress((void**)&oHT,  g_outHT);
    cudaGetSymbolAddress((void**)&scH,  g_scH);
    cudaGetSymbolAddress((void**)&scW,  g_scW);
    cudaGetSymbolAddress((void**)&bnsW, g_bnsW);
    cudaGetSymbolAddress((void**)&bnsH, g_bnsH);
    cudaGetSymbolAddress((void**)&wph,  g_wph);
    cudaGetSymbolAddress((void**)&bp,   g_bp);

    cudaFuncSetAttribute(gemm_kernel, cudaFuncAttributeMaxDynamicSharedMemorySize, GEMM_SMEM);
    cudaFuncSetAttribute(attn_mma_kernel, cudaFuncAttributeMaxDynamicSharedMemorySize, ATT3_SMEM);

    cudaMemsetAsync(bnsW, 0, 512 * sizeof(float));
    cudaMemsetAsync(bnsH, 0, 512 * sizeof(float));

    prepw_one<<<512, 256>>>(wq, bq, wph, bp, 0,   256);
    prepw_one<<<512, 256>>>(wk, bk, wph, bp, 256, 256);
    prepw_one<<<256, 256>>>(wv, bv, wph, bp, 512, 128);
    // #6 (profiled): GEMM — fp16 2-term, 256 threads, 64 px, 2 CTAs/SM
    gemm_kernel<<<dim3(256, 8), 256, GEMM_SMEM>>>(x, wph, bp, qp, kp, vp);

    attn_mma_kernel<<<dim3(128, 8, 4), 256, ATT3_SMEM>>>(qp,  kp,  vp,  oW,  bnsW);
    transpose_kernel<<<dim3(16, 2048), dim3(32,8)>>>((const float*)qp, (float*)qpT);
    transpose_kernel<<<dim3(16, 2048), dim3(32,8)>>>((const float*)kp, (float*)kpT);
    transpose_kernel<<<dim3(16, 1024), dim3(32,8)>>>((const float*)vp, (float*)vpT);
    attn_mma_kernel<<<dim3(128, 8, 4), 256, ATT3_SMEM>>>(qpT, kpT, vpT, oHT, bnsH);

    bn_finalize_kernel<<<1, 256>>>(bnsW, bnsH, bnh_w, bnh_b, bnw_w, bnw_b, scH, scW);
    final_fused_kernel<<<dim3(16, 256, 4), dim3(32, 8)>>>(x, oHT, oW, scH, scW, gamma, out);
}